// round 6
// baseline (speedup 1.0000x reference)
#include <cuda_runtime.h>
#include <cuda_fp16.h>
#include <math.h>
#include <stdint.h>

// Problem constants
#define BB 4
#define TT 8192
#define CC 128
#define RRC 64       // residual channels
#define SSC 256      // skip channels
#define LLC 16

// Output region offsets (pytree flatten order: out, in_acts, cond)
#define OUT_SZ     (BB*256*TT)
#define INACT_OFF  (OUT_SZ)
#define INACT_SZ   (BB*LLC*128*TT)
#define COND_OFF   (INACT_OFF + INACT_SZ)

#define SQRT_HALF 0.70710678118654752440f

// Scratch (device globals; no allocation allowed)
__device__ float g_x0[BB*RRC*TT];
__device__ float g_x1[BB*RRC*TT];

// Pre-packed A-operand fragments (fp16 hi/lo), mma.m16n8k16 layout.
__device__ uint4 g_wd_h[LLC*2048];
__device__ uint4 g_wd_l[LLC*2048];
__device__ uint4 g_ws_h[LLC*2048];
__device__ uint4 g_ws_l[LLC*2048];
__device__ uint4 g_wr_h[15*512];
__device__ uint4 g_wr_l[15*512];
__device__ uint4 g_wo_h[8192];     // conv_out_W frags (hi only)
__device__ uint4 g_we_h[8192];     // conv_end_W frags (hi only)

// ===========================================================================
// helpers
// ===========================================================================
__device__ __forceinline__ uint32_t smem_u32(const void* p) {
    uint32_t a;
    asm("{ .reg .u64 t; cvta.to.shared.u64 t, %1; cvt.u32.u64 %0, t; }" : "=r"(a) : "l"(p));
    return a;
}
__device__ __forceinline__ void ldsm4(uint32_t* r, uint32_t a) {
    asm volatile("ldmatrix.sync.aligned.m8n8.x4.shared.b16 {%0,%1,%2,%3}, [%4];"
        : "=r"(r[0]), "=r"(r[1]), "=r"(r[2]), "=r"(r[3]) : "r"(a));
}
__device__ __forceinline__ void mma16816(float* d, const uint32_t* a, const uint32_t* b) {
    asm volatile(
        "mma.sync.aligned.m16n8k16.row.col.f32.f16.f16.f32 "
        "{%0,%1,%2,%3}, {%4,%5,%6,%7}, {%8,%9}, {%0,%1,%2,%3};"
        : "+f"(d[0]), "+f"(d[1]), "+f"(d[2]), "+f"(d[3])
        : "r"(a[0]), "r"(a[1]), "r"(a[2]), "r"(a[3]), "r"(b[0]), "r"(b[1]));
}
// A fragment (m16 x k16) from row-major [m][k] smem (used by cond kernel)
__device__ __forceinline__ void ldA(uint32_t* fr, const char* sb, int off, int stride,
                                    int m0, int k0, int lane) {
    uint32_t a = smem_u32(sb + off) +
        (uint32_t)(((m0 + (lane & 15)) * stride + k0 + ((lane >> 4) * 8)) << 1);
    ldsm4(fr, a);
}
// B fragments for TWO n8 tiles from row-major [n][k] smem
__device__ __forceinline__ void ldB(uint32_t* fr, const char* sb, int off, int stride,
                                    int n0, int k0, int lane) {
    uint32_t a = smem_u32(sb + off) +
        (uint32_t)(((n0 + ((lane >> 4) & 1) * 8 + (lane & 7)) * stride
                    + k0 + ((lane >> 3) & 1) * 8) << 1);
    ldsm4(fr, a);
}
__device__ __forceinline__ void split2(float v, __half& h, __half& l) {
    h = __float2half_rn(v);
    l = __float2half_rn(v - __half2float(h));
}
__device__ __forceinline__ uint32_t packh2(__half a, __half b) {
    __half2 h = __halves2half2(a, b);
    return *(uint32_t*)&h;
}

// ===========================================================================
// weight pre-pack kernels (mma A-fragment layout)
// ===========================================================================
__device__ __forceinline__ void pack8(const float* v, uint4& hi, uint4& lo) {
    __half eh[8], el[8];
    #pragma unroll
    for (int i = 0; i < 8; i++) split2(v[i], eh[i], el[i]);
    hi.x = packh2(eh[0], eh[1]); hi.y = packh2(eh[2], eh[3]);
    hi.z = packh2(eh[4], eh[5]); hi.w = packh2(eh[6], eh[7]);
    lo.x = packh2(el[0], el[1]); lo.y = packh2(el[2], el[3]);
    lo.z = packh2(el[4], el[5]); lo.w = packh2(el[6], el[7]);
}

__global__ void pack_dilate(const float* __restrict__ dilate_W,
                            uint4* __restrict__ outh, uint4* __restrict__ outl)
{
    int idx = blockIdx.x * 256 + threadIdx.x;   // 16*8*8*32 = 32768
    int lane = idx & 31, fi = idx >> 5;
    int ks = fi & 7, mt = (fi >> 3) & 7, l = fi >> 6;
    int r = mt*16 + (lane >> 2), cb = ks*16 + (lane & 3)*2;
    int dr[8] = {0,0,8,8,0,0,8,8};
    int dc[8] = {0,1,0,1,8,9,8,9};
    float v[8];
    #pragma unroll
    for (int i = 0; i < 8; i++) {
        int row = r + dr[i], col = cb + dc[i];
        v[i] = (col < 64)
            ? dilate_W[((l*128 + row)*64 + col)*2 + 0]
            : dilate_W[((l*128 + row)*64 + (col - 64))*2 + 1];
    }
    uint4 hi, lo; pack8(v, hi, lo);
    outh[idx] = hi; outl[idx] = lo;
}

__global__ void pack_skip(const float* __restrict__ skip_W,
                          uint4* __restrict__ outh, uint4* __restrict__ outl)
{
    int idx = blockIdx.x * 256 + threadIdx.x;   // 16*16*4*32 = 32768
    int lane = idx & 31, fi = idx >> 5;
    int ks = fi & 3, mt = (fi >> 2) & 15, l = fi >> 6;
    int r = mt*16 + (lane >> 2), cb = ks*16 + (lane & 3)*2;
    int dr[8] = {0,0,8,8,0,0,8,8};
    int dc[8] = {0,1,0,1,8,9,8,9};
    float v[8];
    #pragma unroll
    for (int i = 0; i < 8; i++)
        v[i] = skip_W[((size_t)l*256 + r + dr[i])*64 + cb + dc[i]];
    uint4 hi, lo; pack8(v, hi, lo);
    outh[idx] = hi; outl[idx] = lo;
}

__global__ void pack_res(const float* __restrict__ res_W,
                         uint4* __restrict__ outh, uint4* __restrict__ outl)
{
    int idx = blockIdx.x * 256 + threadIdx.x;   // 15*4*4*32 = 7680
    if (idx >= 7680) return;
    int lane = idx & 31, fi = idx >> 5;
    int ks = fi & 3, mt = (fi >> 2) & 3, l = fi >> 4;
    int r = mt*16 + (lane >> 2), cb = ks*16 + (lane & 3)*2;
    int dr[8] = {0,0,8,8,0,0,8,8};
    int dc[8] = {0,1,0,1,8,9,8,9};
    float v[8];
    #pragma unroll
    for (int i = 0; i < 8; i++)
        v[i] = res_W[((size_t)l*64 + r + dr[i])*64 + cb + dc[i]];
    uint4 hi, lo; pack8(v, hi, lo);
    outh[idx] = hi; outl[idx] = lo;
}

// [256][256] row-major weight -> hi-only frags, idx = (mt*16+ks)*32+lane
__global__ void pack_w256(const float* __restrict__ W, uint4* __restrict__ outh)
{
    int idx = blockIdx.x * 256 + threadIdx.x;   // 16*16*32 = 8192
    int lane = idx & 31, fi = idx >> 5;
    int ks = fi & 15, mt = fi >> 4;
    int r = mt*16 + (lane >> 2), cb = ks*16 + (lane & 3)*2;
    int dr[8] = {0,0,8,8,0,0,8,8};
    int dc[8] = {0,1,0,1,8,9,8,9};
    __half eh[8];
    #pragma unroll
    for (int i = 0; i < 8; i++)
        eh[i] = __float2half_rn(W[(r + dr[i])*256 + cb + dc[i]]);
    uint4 hi;
    hi.x = packh2(eh[0], eh[1]); hi.y = packh2(eh[2], eh[3]);
    hi.z = packh2(eh[4], eh[5]); hi.w = packh2(eh[6], eh[7]);
    outh[idx] = hi;
}

// ===========================================================================
// embed
// ===========================================================================
__global__ void embed_kernel(const int* __restrict__ tokens,
                             const float* __restrict__ embed,
                             float* __restrict__ x0)
{
    __shared__ int tok[256];
    const int t0 = blockIdx.x * 256;
    const int b  = blockIdx.y;
    tok[threadIdx.x] = tokens[b*TT + t0 + threadIdx.x];
    __syncthreads();
    const int v = tok[threadIdx.x];
    #pragma unroll 4
    for (int r = 0; r < RRC; r++)
        x0[(b*RRC + r)*TT + t0 + threadIdx.x] = embed[v*RRC + r];
}

// ===========================================================================
// cond (mma fp16 3-pass), unchanged
// ===========================================================================
#define CO_WH 0
#define CO_WL 34816
#define CO_FH 69632
#define CO_FL 104448
#define CO_SMEM 139264

__global__ void __launch_bounds__(512)
cond_mma_kernel(const float* __restrict__ features,
                const float* __restrict__ cond_W,
                const float* __restrict__ cond_b,
                float* __restrict__ cond_out)
{
    extern __shared__ char sb[];
    __half* WH = (__half*)(sb + CO_WH);
    __half* WL = (__half*)(sb + CO_WL);
    __half* FH = (__half*)(sb + CO_FH);
    __half* FL = (__half*)(sb + CO_FL);

    const int tid = threadIdx.x, wid = tid >> 5, lane = tid & 31;
    const int g = lane >> 2, tg = lane & 3;
    const int t0 = blockIdx.x * 128;
    const int l  = blockIdx.y;
    const int b  = blockIdx.z;

    const float* Wp = cond_W + (size_t)l * 128 * CC;
    for (int e = tid; e < 16384; e += 512) {
        int o = e >> 7, k = e & 127;
        __half h, lo; split2(Wp[e], h, lo);
        WH[o*136 + k] = h; WL[o*136 + k] = lo;
    }
    for (int e = tid; e < 16384; e += 512) {
        int t = e & 127, k = e >> 7;
        float v = features[((size_t)b*CC + k)*TT + t0 + t];
        __half h, lo; split2(v, h, lo);
        FH[t*136 + k] = h; FL[t*136 + k] = lo;
    }
    __syncthreads();

    const int mi = wid >> 2, ni = wid & 3;
    const int m0 = mi * 32, n0 = ni * 32;
    float acc[2][4][4] = {};

    for (int ks = 0; ks < 8; ks++) {
        int k0 = ks * 16;
        uint32_t ah[2][4], al[2][4];
        ldA(ah[0], sb, CO_WH, 136, m0,      k0, lane);
        ldA(ah[1], sb, CO_WH, 136, m0 + 16, k0, lane);
        ldA(al[0], sb, CO_WL, 136, m0,      k0, lane);
        ldA(al[1], sb, CO_WL, 136, m0 + 16, k0, lane);
        #pragma unroll
        for (int p = 0; p < 2; p++) {
            uint32_t bh[4], bl[4];
            ldB(bh, sb, CO_FH, 136, n0 + p*16, k0, lane);
            ldB(bl, sb, CO_FL, 136, n0 + p*16, k0, lane);
            #pragma unroll
            for (int mt = 0; mt < 2; mt++)
                #pragma unroll
                for (int q = 0; q < 2; q++) {
                    int nt = p*2 + q;
                    mma16816(acc[mt][nt], ah[mt], &bh[q*2]);
                    mma16816(acc[mt][nt], ah[mt], &bl[q*2]);
                    mma16816(acc[mt][nt], al[mt], &bh[q*2]);
                }
        }
    }

    #pragma unroll
    for (int mt = 0; mt < 2; mt++)
        #pragma unroll
        for (int r = 0; r < 2; r++) {
            int o = m0 + mt*16 + r*8 + g;
            float bias = cond_b[l*128 + o];
            float* row = cond_out + ((size_t)(b*LLC + l)*128 + o)*TT + t0;
            #pragma unroll
            for (int nt = 0; nt < 4; nt++) {
                int tc = n0 + nt*8 + 2*tg;
                float2 rv = make_float2(acc[mt][nt][r*2+0] + bias,
                                        acc[mt][nt][r*2+1] + bias);
                *(float2*)(row + tc) = rv;
            }
        }
}

// ===========================================================================
// layer v3: 256 threads, t-tile 64. No skip GEMM. cond staged to smem up front.
// grid (T/64=128, B), 3 CTAs/SM
// smem phase1: XH[64][136] 17408, XL 17408, CND fp32[128][66] 33792 @34816
// smem phase2: ABUF fp32[128][66] @0 (33792), AH[64][72] @33792, AL @43008
// ===========================================================================
#define L3_XH   0
#define L3_XL   17408
#define L3_CND  34816
#define L3_ABUF 0
#define L3_AH   33792
#define L3_AL   43008
#define L3_SMEM 68608

__global__ void __launch_bounds__(256, 3)
layer_mma3_kernel(const float* __restrict__ x_in,
                  float* __restrict__ x_out,
                  const uint4* __restrict__ wd_h, const uint4* __restrict__ wd_l,
                  const float* __restrict__ dilate_b,
                  const uint4* __restrict__ wr_h, const uint4* __restrict__ wr_l,
                  const float* __restrict__ res_b,
                  const float* __restrict__ cond_g,
                  float* __restrict__ inacts_g,
                  int layer, int dil, int last)
{
    extern __shared__ char sb[];
    const int tid = threadIdx.x, wid = tid >> 5, lane = tid & 31;
    const int g = lane >> 2, tg = lane & 3;
    const int t0 = blockIdx.x * 64;
    const int b  = blockIdx.y;

    // ---- stage X halves + cond tile
    {
        __half* XH = (__half*)(sb + L3_XH);
        __half* XL = (__half*)(sb + L3_XL);
        const float* xb = x_in + (size_t)b * RRC * TT;
        for (int e = tid; e < 8192; e += 256) {
            int t = e & 63, ks = e >> 6;
            float v;
            if (ks < 64) {
                int tp = t0 + t - dil;
                v = (tp >= 0) ? xb[ks*TT + tp] : 0.f;
            } else {
                v = xb[(ks - 64)*TT + t0 + t];
            }
            __half h, lo; split2(v, h, lo);
            XH[t*136 + ks] = h; XL[t*136 + ks] = lo;
        }
        float* CND = (float*)(sb + L3_CND);
        const float* cbase = cond_g + ((size_t)(b*LLC + layer)*128)*TT + t0;
        for (int e = tid; e < 8192; e += 256) {
            int t = e & 63, o = e >> 6;
            CND[o*66 + t] = cbase[(size_t)o*TT + t];
        }
    }
    __syncthreads();

    const int mi = wid >> 1, ni = wid & 1;
    const int m0 = mi * 32, n0 = ni * 32;

    // ---- GEMM1: ia[128 o][64 t] = Wd @ Xcat (K=128), 3-pass
    float acc[2][4][4] = {};
    {
        const uint4* ph = wd_h + (size_t)layer * 2048;
        const uint4* pl = wd_l + (size_t)layer * 2048;
        for (int ks = 0; ks < 8; ks++) {
            uint4 A0h = ph[((mi*2    )*8 + ks)*32 + lane];
            uint4 A1h = ph[((mi*2 + 1)*8 + ks)*32 + lane];
            uint4 A0l = pl[((mi*2    )*8 + ks)*32 + lane];
            uint4 A1l = pl[((mi*2 + 1)*8 + ks)*32 + lane];
            #pragma unroll
            for (int p = 0; p < 2; p++) {
                uint32_t bh[4], bl[4];
                ldB(bh, sb, L3_XH, 136, n0 + p*16, ks*16, lane);
                ldB(bl, sb, L3_XL, 136, n0 + p*16, ks*16, lane);
                #pragma unroll
                for (int q = 0; q < 2; q++) {
                    int nt = p*2 + q;
                    mma16816(acc[0][nt], (const uint32_t*)&A0h, &bh[q*2]);
                    mma16816(acc[0][nt], (const uint32_t*)&A0h, &bl[q*2]);
                    mma16816(acc[0][nt], (const uint32_t*)&A0l, &bh[q*2]);
                    mma16816(acc[1][nt], (const uint32_t*)&A1h, &bh[q*2]);
                    mma16816(acc[1][nt], (const uint32_t*)&A1h, &bl[q*2]);
                    mma16816(acc[1][nt], (const uint32_t*)&A1l, &bh[q*2]);
                }
            }
        }
    }
    __syncthreads();   // all X reads done before abuf aliases X

    // ---- epilogue1: ia -> gmem in_acts; a = ia + cond(smem) -> abuf
    {
        float* abuf = (float*)(sb + L3_ABUF);
        const float* CND = (const float*)(sb + L3_CND);
        #pragma unroll
        for (int mt = 0; mt < 2; mt++)
            #pragma unroll
            for (int r = 0; r < 2; r++) {
                int o = m0 + mt*16 + r*8 + g;
                float bias = dilate_b[layer*128 + o];
                float* iap = inacts_g + ((size_t)(b*LLC + layer)*128 + o)*TT + t0;
                float* ab = abuf + o*66;
                const float* cp = CND + o*66;
                #pragma unroll
                for (int nt = 0; nt < 4; nt++) {
                    int tc = n0 + nt*8 + 2*tg;
                    float ia0 = acc[mt][nt][r*2+0] + bias;
                    float ia1 = acc[mt][nt][r*2+1] + bias;
                    *(float2*)(iap + tc) = make_float2(ia0, ia1);
                    float2 cv = *(const float2*)(cp + tc);
                    *(float2*)(ab + tc) = make_float2(ia0 + cv.x, ia1 + cv.y);
                }
            }
    }
    if (last) return;   // uniform branch; acts/res not needed after last layer
    __syncthreads();

    // ---- gated activation -> AH/AL
    {
        float* abuf = (float*)(sb + L3_ABUF);
        __half* AH = (__half*)(sb + L3_AH);
        __half* AL = (__half*)(sb + L3_AL);
        for (int e = tid; e < 4096; e += 256) {
            int t = e & 63, kk = e >> 6;
            float a0 = abuf[kk*66 + t];
            float a1 = abuf[(kk + 64)*66 + t];
            float act = tanhf(a0) * (1.f / (1.f + __expf(-a1)));
            __half h, lo; split2(act, h, lo);
            AH[t*72 + kk] = h; AL[t*72 + kk] = lo;
        }
    }
    __syncthreads();

    // ---- GEMM3: res (M=64, K=64), 3-pass; residual x update
    {
        const int mi3 = wid >> 2, ni3 = wid & 3;
        const int m0r = mi3 * 32, n0r = ni3 * 16;
        const uint4* ph = wr_h + (size_t)layer * 512;
        const uint4* pl = wr_l + (size_t)layer * 512;
        float acc3[2][2][4] = {};
        for (int ks = 0; ks < 4; ks++) {
            uint4 A0h = ph[((mi3*2    )*4 + ks)*32 + lane];
            uint4 A1h = ph[((mi3*2 + 1)*4 + ks)*32 + lane];
            uint4 A0l = pl[((mi3*2    )*4 + ks)*32 + lane];
            uint4 A1l = pl[((mi3*2 + 1)*4 + ks)*32 + lane];
            uint32_t bh[4], bl[4];
            ldB(bh, sb, L3_AH, 72, n0r, ks*16, lane);
            ldB(bl, sb, L3_AL, 72, n0r, ks*16, lane);
            #pragma unroll
            for (int q = 0; q < 2; q++) {
                mma16816(acc3[0][q], (const uint32_t*)&A0h, &bh[q*2]);
                mma16816(acc3[0][q], (const uint32_t*)&A0h, &bl[q*2]);
                mma16816(acc3[0][q], (const uint32_t*)&A0l, &bh[q*2]);
                mma16816(acc3[1][q], (const uint32_t*)&A1h, &bh[q*2]);
                mma16816(acc3[1][q], (const uint32_t*)&A1h, &bl[q*2]);
                mma16816(acc3[1][q], (const uint32_t*)&A1l, &bh[q*2]);
            }
        }
        #pragma unroll
        for (int mt = 0; mt < 2; mt++)
            #pragma unroll
            for (int r = 0; r < 2; r++) {
                int o = m0r + mt*16 + r*8 + g;
                float rb = res_b[layer*RRC + o];
                const float* xi = x_in  + ((size_t)b*RRC + o)*TT + t0;
                float*       xo = x_out + ((size_t)b*RRC + o)*TT + t0;
                #pragma unroll
                for (int nt = 0; nt < 2; nt++) {
                    int tc = n0r + nt*8 + 2*tg;
                    float2 xv = *(const float2*)(xi + tc);
                    float2 rv;
                    rv.x = (acc3[mt][nt][r*2+0] + rb + xv.x) * SQRT_HALF;
                    rv.y = (acc3[mt][nt][r*2+1] + rb + xv.y) * SQRT_HALF;
                    *(float2*)(xo + tc) = rv;
                }
            }
    }
}

// ===========================================================================
// skip + head tail kernel:
// skip_out = sum_l Ws_l @ gated(in_acts_l + cond_l) + sum_l b_l
// h = relu(skip_out); h2 = relu(Wout@h); out = Wend@h2 shifted right by 1.
// grid (T/64=128, B), 256 threads. Warp w owns o-slice [w*32, w*32+32).
// smem: AH[64][72] @0, AL @9216 (layer loop); H[64][264] @0 (head, aliased)
// ===========================================================================
#define T_AH 0
#define T_AL 9216
#define T_H  0
#define T_SMEM 33792

__global__ void __launch_bounds__(256, 2)
skiphead_kernel(const float* __restrict__ inacts_g,
                const float* __restrict__ cond_g,
                const uint4* __restrict__ ws_h, const uint4* __restrict__ ws_l,
                const float* __restrict__ skip_b,
                const uint4* __restrict__ wo_h, const uint4* __restrict__ we_h,
                float* __restrict__ out)
{
    extern __shared__ char sb[];
    const int tid = threadIdx.x, wid = tid >> 5, lane = tid & 31;
    const int g = lane >> 2, tg = lane & 3;
    const int t0 = blockIdx.x * 64;
    const int b  = blockIdx.y;

    float acc[2][8][4] = {};   // skip accumulator: o = wid*32 + mt*16 + r*8 + g

    for (int l = 0; l < LLC; l++) {
        // recompute acts for this layer tile
        {
            __half* AH = (__half*)(sb + T_AH);
            __half* AL = (__half*)(sb + T_AL);
            const size_t lbase = ((size_t)(b*LLC + l)*128)*TT + t0;
            for (int e = tid; e < 4096; e += 256) {
                int t = e & 63, kk = e >> 6;
                size_t p0 = lbase + (size_t)kk*TT + t;
                size_t p1 = p0 + (size_t)64*TT;
                float a0 = inacts_g[p0] + cond_g[p0];
                float a1 = inacts_g[p1] + cond_g[p1];
                float act = tanhf(a0) * (1.f / (1.f + __expf(-a1)));
                __half h, lo; split2(act, h, lo);
                AH[t*72 + kk] = h; AL[t*72 + kk] = lo;
            }
        }
        __syncthreads();
        // accumulate Ws_l @ acts (3-pass)
        {
            const uint4* ph = ws_h + (size_t)l * 2048;
            const uint4* pl = ws_l + (size_t)l * 2048;
            for (int ks = 0; ks < 4; ks++) {
                uint4 A0h = ph[((wid*2    )*4 + ks)*32 + lane];
                uint4 A1h = ph[((wid*2 + 1)*4 + ks)*32 + lane];
                uint4 A0l = pl[((wid*2    )*4 + ks)*32 + lane];
                uint4 A1l = pl[((wid*2 + 1)*4 + ks)*32 + lane];
                #pragma unroll
                for (int p = 0; p < 4; p++) {
                    uint32_t bh[4], bl[4];
                    ldB(bh, sb, T_AH, 72, p*16, ks*16, lane);
                    ldB(bl, sb, T_AL, 72, p*16, ks*16, lane);
                    #pragma unroll
                    for (int q = 0; q < 2; q++) {
                        int nt = p*2 + q;
                        mma16816(acc[0][nt], (const uint32_t*)&A0h, &bh[q*2]);
                        mma16816(acc[0][nt], (const uint32_t*)&A0h, &bl[q*2]);
                        mma16816(acc[0][nt], (const uint32_t*)&A0l, &bh[q*2]);
                        mma16816(acc[1][nt], (const uint32_t*)&A1h, &bh[q*2]);
                        mma16816(acc[1][nt], (const uint32_t*)&A1h, &bl[q*2]);
                        mma16816(acc[1][nt], (const uint32_t*)&A1l, &bh[q*2]);
                    }
                }
            }
        }
        __syncthreads();   // before next layer overwrites AH/AL
    }

    // skip bias sum + relu -> H as fp16 [t][o 0..255]
    {
        __half* H = (__half*)(sb + T_H);
        #pragma unroll
        for (int mt = 0; mt < 2; mt++)
            #pragma unroll
            for (int r = 0; r < 2; r++) {
                int o = wid*32 + mt*16 + r*8 + g;
                float bs = 0.f;
                #pragma unroll
                for (int l = 0; l < LLC; l++) bs += skip_b[l*SSC + o];
                #pragma unroll
                for (int nt = 0; nt < 8; nt++) {
                    int t = nt*8 + tg*2;
                    H[t*264 + o]     = __float2half_rn(fmaxf(acc[mt][nt][r*2+0] + bs, 0.f));
                    H[(t+1)*264 + o] = __float2half_rn(fmaxf(acc[mt][nt][r*2+1] + bs, 0.f));
                }
            }
    }
    __syncthreads();

    // head GEMM A: h2 = relu(Wout @ h)  (M=256, N=64, K=256, single-pass)
    float acc2[2][8][4] = {};
    for (int ks = 0; ks < 16; ks++) {
        uint4 A0 = wo_h[((wid*2    )*16 + ks)*32 + lane];
        uint4 A1 = wo_h[((wid*2 + 1)*16 + ks)*32 + lane];
        #pragma unroll
        for (int p = 0; p < 4; p++) {
            uint32_t bh[4];
            ldB(bh, sb, T_H, 264, p*16, ks*16, lane);
            #pragma unroll
            for (int q = 0; q < 2; q++) {
                int nt = p*2 + q;
                mma16816(acc2[0][nt], (const uint32_t*)&A0, &bh[q*2]);
                mma16816(acc2[1][nt], (const uint32_t*)&A1, &bh[q*2]);
            }
        }
    }
    __syncthreads();
    {
        __half* H = (__half*)(sb + T_H);
        #pragma unroll
        for (int mt = 0; mt < 2; mt++)
            #pragma unroll
            for (int r = 0; r < 2; r++) {
                int o = wid*32 + mt*16 + r*8 + g;
                #pragma unroll
                for (int nt = 0; nt < 8; nt++) {
                    int t = nt*8 + tg*2;
                    H[t*264 + o]     = __float2half_rn(fmaxf(acc2[mt][nt][r*2+0], 0.f));
                    H[(t+1)*264 + o] = __float2half_rn(fmaxf(acc2[mt][nt][r*2+1], 0.f));
                }
            }
    }
    __syncthreads();

    // head GEMM B: out = Wend @ h2, shifted right by 1
    float acc3[2][8][4] = {};
    for (int ks = 0; ks < 16; ks++) {
        uint4 A0 = we_h[((wid*2    )*16 + ks)*32 + lane];
        uint4 A1 = we_h[((wid*2 + 1)*16 + ks)*32 + lane];
        #pragma unroll
        for (int p = 0; p < 4; p++) {
            uint32_t bh[4];
            ldB(bh, sb, T_H, 264, p*16, ks*16, lane);
            #pragma unroll
            for (int q = 0; q < 2; q++) {
                int nt = p*2 + q;
                mma16816(acc3[0][nt], (const uint32_t*)&A0, &bh[q*2]);
                mma16816(acc3[1][nt], (const uint32_t*)&A1, &bh[q*2]);
            }
        }
    }
    #pragma unroll
    for (int mt = 0; mt < 2; mt++)
        #pragma unroll
        for (int r = 0; r < 2; r++) {
            int o = wid*32 + mt*16 + r*8 + g;
            float* op = out + ((size_t)b*256 + o)*TT;
            #pragma unroll
            for (int nt = 0; nt < 8; nt++) {
                int tc = t0 + nt*8 + 2*tg;
                if (tc + 1 < TT) op[tc + 1] = acc3[mt][nt][r*2+0];
                if (tc + 2 < TT) op[tc + 2] = acc3[mt][nt][r*2+1];
            }
        }
    if (blockIdx.x == 0) out[((size_t)b*256 + tid)*TT] = 0.f;
}

// ===========================================================================
extern "C" void kernel_launch(void* const* d_in, const int* in_sizes, int n_in,
                              void* d_out, int out_size)
{
    const float* features   = (const float*)d_in[0];
    const int*   tokens     = (const int*)  d_in[1];
    const float* embed      = (const float*)d_in[2];
    const float* cond_W     = (const float*)d_in[3];
    const float* cond_b     = (const float*)d_in[4];
    const float* dilate_W   = (const float*)d_in[5];
    const float* dilate_b   = (const float*)d_in[6];
    const float* res_W      = (const float*)d_in[7];
    const float* res_b      = (const float*)d_in[8];
    const float* skip_W     = (const float*)d_in[9];
    const float* skip_b     = (const float*)d_in[10];
    const float* conv_out_W = (const float*)d_in[11];
    const float* conv_end_W = (const float*)d_in[12];
    float* outp = (float*)d_out;

    float* out_r   = outp;
    float* inact_r = outp + INACT_OFF;
    float* cond_r  = outp + COND_OFF;

    float *x0, *x1;
    uint4 *wdh, *wdl, *wsh, *wsl, *wrh, *wrl, *woh, *weh;
    cudaGetSymbolAddress((void**)&x0,  g_x0);
    cudaGetSymbolAddress((void**)&x1,  g_x1);
    cudaGetSymbolAddress((void**)&wdh, g_wd_h);
    cudaGetSymbolAddress((void**)&wdl, g_wd_l);
    cudaGetSymbolAddress((void**)&wsh, g_ws_h);
    cudaGetSymbolAddress((void**)&wsl, g_ws_l);
    cudaGetSymbolAddress((void**)&wrh, g_wr_h);
    cudaGetSymbolAddress((void**)&wrl, g_wr_l);
    cudaGetSymbolAddress((void**)&woh, g_wo_h);
    cudaGetSymbolAddress((void**)&weh, g_we_h);

    static const int DIL[LLC] = {1,2,4,8,16,32,64,128,256,1,2,4,8,16,32,64};

    cudaFuncSetAttribute(cond_mma_kernel,   cudaFuncAttributeMaxDynamicSharedMemorySize, CO_SMEM);
    cudaFuncSetAttribute(layer_mma3_kernel, cudaFuncAttributeMaxDynamicSharedMemorySize, L3_SMEM);
    cudaFuncSetAttribute(skiphead_kernel,   cudaFuncAttributeMaxDynamicSharedMemorySize, T_SMEM);

    pack_dilate<<<128, 256>>>(dilate_W, wdh, wdl);
    pack_skip<<<128, 256>>>(skip_W, wsh, wsl);
    pack_res<<<30, 256>>>(res_W, wrh, wrl);
    pack_w256<<<32, 256>>>(conv_out_W, woh);
    pack_w256<<<32, 256>>>(conv_end_W, weh);

    embed_kernel<<<dim3(TT/256, BB), 256>>>(tokens, embed, x0);
    cond_mma_kernel<<<dim3(TT/128, LLC, BB), 512, CO_SMEM>>>(features, cond_W, cond_b, cond_r);

    float* xi = x0;
    float* xo = x1;
    for (int i = 0; i < LLC; i++) {
        layer_mma3_kernel<<<dim3(TT/64, BB), 256, L3_SMEM>>>(
            xi, xo, wdh, wdl, dilate_b, wrh, wrl, res_b,
            cond_r, inact_r,
            i, DIL[i], (i == LLC-1) ? 1 : 0);
        float* t = xi; xi = xo; xo = t;
    }

    skiphead_kernel<<<dim3(TT/64, BB), 256, T_SMEM>>>(
        inact_r, cond_r, wsh, wsl, skip_b, woh, weh, out_r);
}

// round 8
// speedup vs baseline: 1.3298x; 1.3298x over previous
#include <cuda_runtime.h>
#include <cuda_fp16.h>
#include <math.h>
#include <stdint.h>

// Problem constants
#define BB 4
#define TT 8192
#define CC 128
#define RRC 64       // residual channels
#define SSC 256      // skip channels
#define LLC 16

// Output region offsets (pytree flatten order: out, in_acts, cond)
#define OUT_SZ     (BB*256*TT)
#define INACT_OFF  (OUT_SZ)
#define INACT_SZ   (BB*LLC*128*TT)
#define COND_OFF   (INACT_OFF + INACT_SZ)

#define SQRT_HALF 0.70710678118654752440f

// Scratch (device globals; no allocation allowed)
__device__ float g_x0[BB*RRC*TT];
__device__ float g_x1[BB*RRC*TT];

// Gated activations, fp16 hi/lo planes, layout [l][b][t][64ch]
__device__ __align__(16) __half g_act_h[LLC*BB*TT*64];
__device__ __align__(16) __half g_act_l[LLC*BB*TT*64];

// Pre-packed A-operand fragments (fp16 hi/lo), mma.m16n8k16 layout.
__device__ uint4 g_wd_h[LLC*2048];
__device__ uint4 g_wd_l[LLC*2048];
__device__ uint4 g_ws_h[LLC*2048];
__device__ uint4 g_ws_l[LLC*2048];
__device__ uint4 g_wr_h[15*512];
__device__ uint4 g_wr_l[15*512];
__device__ uint4 g_wo_h[8192];     // conv_out_W frags (hi only)
__device__ uint4 g_we_h[8192];     // conv_end_W frags (hi only)

// ===========================================================================
// helpers
// ===========================================================================
__device__ __forceinline__ uint32_t smem_u32(const void* p) {
    uint32_t a;
    asm("{ .reg .u64 t; cvta.to.shared.u64 t, %1; cvt.u32.u64 %0, t; }" : "=r"(a) : "l"(p));
    return a;
}
__device__ __forceinline__ void ldsm4(uint32_t* r, uint32_t a) {
    asm volatile("ldmatrix.sync.aligned.m8n8.x4.shared.b16 {%0,%1,%2,%3}, [%4];"
        : "=r"(r[0]), "=r"(r[1]), "=r"(r[2]), "=r"(r[3]) : "r"(a));
}
__device__ __forceinline__ void mma16816(float* d, const uint32_t* a, const uint32_t* b) {
    asm volatile(
        "mma.sync.aligned.m16n8k16.row.col.f32.f16.f16.f32 "
        "{%0,%1,%2,%3}, {%4,%5,%6,%7}, {%8,%9}, {%0,%1,%2,%3};"
        : "+f"(d[0]), "+f"(d[1]), "+f"(d[2]), "+f"(d[3])
        : "r"(a[0]), "r"(a[1]), "r"(a[2]), "r"(a[3]), "r"(b[0]), "r"(b[1]));
}
__device__ __forceinline__ void ldA(uint32_t* fr, const char* sb, int off, int stride,
                                    int m0, int k0, int lane) {
    uint32_t a = smem_u32(sb + off) +
        (uint32_t)(((m0 + (lane & 15)) * stride + k0 + ((lane >> 4) * 8)) << 1);
    ldsm4(fr, a);
}
__device__ __forceinline__ void ldB(uint32_t* fr, const char* sb, int off, int stride,
                                    int n0, int k0, int lane) {
    uint32_t a = smem_u32(sb + off) +
        (uint32_t)(((n0 + ((lane >> 4) & 1) * 8 + (lane & 7)) * stride
                    + k0 + ((lane >> 3) & 1) * 8) << 1);
    ldsm4(fr, a);
}
__device__ __forceinline__ void split2(float v, __half& h, __half& l) {
    h = __float2half_rn(v);
    l = __float2half_rn(v - __half2float(h));
}
__device__ __forceinline__ uint32_t packh2(__half a, __half b) {
    __half2 h = __halves2half2(a, b);
    return *(uint32_t*)&h;
}

#define CP_ASYNC16(dst, src) \
    asm volatile("cp.async.ca.shared.global [%0], [%1], 16;" :: "r"(dst), "l"(src))
#define CP_COMMIT() asm volatile("cp.async.commit_group;" ::: "memory")
#define CP_WAIT0()  asm volatile("cp.async.wait_group 0;" ::: "memory")

// ===========================================================================
// weight pre-pack kernels
// ===========================================================================
__device__ __forceinline__ void pack8(const float* v, uint4& hi, uint4& lo) {
    __half eh[8], el[8];
    #pragma unroll
    for (int i = 0; i < 8; i++) split2(v[i], eh[i], el[i]);
    hi.x = packh2(eh[0], eh[1]); hi.y = packh2(eh[2], eh[3]);
    hi.z = packh2(eh[4], eh[5]); hi.w = packh2(eh[6], eh[7]);
    lo.x = packh2(el[0], el[1]); lo.y = packh2(el[2], el[3]);
    lo.z = packh2(el[4], el[5]); lo.w = packh2(el[6], el[7]);
}

__global__ void pack_dilate(const float* __restrict__ dilate_W,
                            uint4* __restrict__ outh, uint4* __restrict__ outl)
{
    int idx = blockIdx.x * 256 + threadIdx.x;
    int lane = idx & 31, fi = idx >> 5;
    int ks = fi & 7, mt = (fi >> 3) & 7, l = fi >> 6;
    int r = mt*16 + (lane >> 2), cb = ks*16 + (lane & 3)*2;
    int dr[8] = {0,0,8,8,0,0,8,8};
    int dc[8] = {0,1,0,1,8,9,8,9};
    float v[8];
    #pragma unroll
    for (int i = 0; i < 8; i++) {
        int row = r + dr[i], col = cb + dc[i];
        v[i] = (col < 64)
            ? dilate_W[((l*128 + row)*64 + col)*2 + 0]
            : dilate_W[((l*128 + row)*64 + (col - 64))*2 + 1];
    }
    uint4 hi, lo; pack8(v, hi, lo);
    outh[idx] = hi; outl[idx] = lo;
}

__global__ void pack_skip(const float* __restrict__ skip_W,
                          uint4* __restrict__ outh, uint4* __restrict__ outl)
{
    int idx = blockIdx.x * 256 + threadIdx.x;
    int lane = idx & 31, fi = idx >> 5;
    int ks = fi & 3, mt = (fi >> 2) & 15, l = fi >> 6;
    int r = mt*16 + (lane >> 2), cb = ks*16 + (lane & 3)*2;
    int dr[8] = {0,0,8,8,0,0,8,8};
    int dc[8] = {0,1,0,1,8,9,8,9};
    float v[8];
    #pragma unroll
    for (int i = 0; i < 8; i++)
        v[i] = skip_W[((size_t)l*256 + r + dr[i])*64 + cb + dc[i]];
    uint4 hi, lo; pack8(v, hi, lo);
    outh[idx] = hi; outl[idx] = lo;
}

__global__ void pack_res(const float* __restrict__ res_W,
                         uint4* __restrict__ outh, uint4* __restrict__ outl)
{
    int idx = blockIdx.x * 256 + threadIdx.x;
    if (idx >= 7680) return;
    int lane = idx & 31, fi = idx >> 5;
    int ks = fi & 3, mt = (fi >> 2) & 3, l = fi >> 4;
    int r = mt*16 + (lane >> 2), cb = ks*16 + (lane & 3)*2;
    int dr[8] = {0,0,8,8,0,0,8,8};
    int dc[8] = {0,1,0,1,8,9,8,9};
    float v[8];
    #pragma unroll
    for (int i = 0; i < 8; i++)
        v[i] = res_W[((size_t)l*64 + r + dr[i])*64 + cb + dc[i]];
    uint4 hi, lo; pack8(v, hi, lo);
    outh[idx] = hi; outl[idx] = lo;
}

__global__ void pack_w256(const float* __restrict__ W, uint4* __restrict__ outh)
{
    int idx = blockIdx.x * 256 + threadIdx.x;
    int lane = idx & 31, fi = idx >> 5;
    int ks = fi & 15, mt = fi >> 4;
    int r = mt*16 + (lane >> 2), cb = ks*16 + (lane & 3)*2;
    int dr[8] = {0,0,8,8,0,0,8,8};
    int dc[8] = {0,1,0,1,8,9,8,9};
    __half eh[8];
    #pragma unroll
    for (int i = 0; i < 8; i++)
        eh[i] = __float2half_rn(W[(r + dr[i])*256 + cb + dc[i]]);
    uint4 hi;
    hi.x = packh2(eh[0], eh[1]); hi.y = packh2(eh[2], eh[3]);
    hi.z = packh2(eh[4], eh[5]); hi.w = packh2(eh[6], eh[7]);
    outh[idx] = hi;
}

// ===========================================================================
// embed
// ===========================================================================
__global__ void embed_kernel(const int* __restrict__ tokens,
                             const float* __restrict__ embed,
                             float* __restrict__ x0)
{
    __shared__ int tok[256];
    const int t0 = blockIdx.x * 256;
    const int b  = blockIdx.y;
    tok[threadIdx.x] = tokens[b*TT + t0 + threadIdx.x];
    __syncthreads();
    const int v = tok[threadIdx.x];
    #pragma unroll 4
    for (int r = 0; r < RRC; r++)
        x0[(b*RRC + r)*TT + t0 + threadIdx.x] = embed[v*RRC + r];
}

// ===========================================================================
// cond (mma fp16 3-pass)
// ===========================================================================
#define CO_WH 0
#define CO_WL 34816
#define CO_FH 69632
#define CO_FL 104448
#define CO_SMEM 139264

__global__ void __launch_bounds__(512)
cond_mma_kernel(const float* __restrict__ features,
                const float* __restrict__ cond_W,
                const float* __restrict__ cond_b,
                float* __restrict__ cond_out)
{
    extern __shared__ char sb[];
    __half* WH = (__half*)(sb + CO_WH);
    __half* WL = (__half*)(sb + CO_WL);
    __half* FH = (__half*)(sb + CO_FH);
    __half* FL = (__half*)(sb + CO_FL);

    const int tid = threadIdx.x, wid = tid >> 5, lane = tid & 31;
    const int g = lane >> 2, tg = lane & 3;
    const int t0 = blockIdx.x * 128;
    const int l  = blockIdx.y;
    const int b  = blockIdx.z;

    const float* Wp = cond_W + (size_t)l * 128 * CC;
    for (int e = tid; e < 16384; e += 512) {
        int o = e >> 7, k = e & 127;
        __half h, lo; split2(Wp[e], h, lo);
        WH[o*136 + k] = h; WL[o*136 + k] = lo;
    }
    for (int e = tid; e < 16384; e += 512) {
        int t = e & 127, k = e >> 7;
        float v = features[((size_t)b*CC + k)*TT + t0 + t];
        __half h, lo; split2(v, h, lo);
        FH[t*136 + k] = h; FL[t*136 + k] = lo;
    }
    __syncthreads();

    const int mi = wid >> 2, ni = wid & 3;
    const int m0 = mi * 32, n0 = ni * 32;
    float acc[2][4][4] = {};

    for (int ks = 0; ks < 8; ks++) {
        int k0 = ks * 16;
        uint32_t ah[2][4], al[2][4];
        ldA(ah[0], sb, CO_WH, 136, m0,      k0, lane);
        ldA(ah[1], sb, CO_WH, 136, m0 + 16, k0, lane);
        ldA(al[0], sb, CO_WL, 136, m0,      k0, lane);
        ldA(al[1], sb, CO_WL, 136, m0 + 16, k0, lane);
        #pragma unroll
        for (int p = 0; p < 2; p++) {
            uint32_t bh[4], bl[4];
            ldB(bh, sb, CO_FH, 136, n0 + p*16, k0, lane);
            ldB(bl, sb, CO_FL, 136, n0 + p*16, k0, lane);
            #pragma unroll
            for (int mt = 0; mt < 2; mt++)
                #pragma unroll
                for (int q = 0; q < 2; q++) {
                    int nt = p*2 + q;
                    mma16816(acc[mt][nt], ah[mt], &bh[q*2]);
                    mma16816(acc[mt][nt], ah[mt], &bl[q*2]);
                    mma16816(acc[mt][nt], al[mt], &bh[q*2]);
                }
        }
    }

    #pragma unroll
    for (int mt = 0; mt < 2; mt++)
        #pragma unroll
        for (int r = 0; r < 2; r++) {
            int o = m0 + mt*16 + r*8 + g;
            float bias = cond_b[l*128 + o];
            float* row = cond_out + ((size_t)(b*LLC + l)*128 + o)*TT + t0;
            #pragma unroll
            for (int nt = 0; nt < 4; nt++) {
                int tc = n0 + nt*8 + 2*tg;
                float2 rv = make_float2(acc[mt][nt][r*2+0] + bias,
                                        acc[mt][nt][r*2+1] + bias);
                *(float2*)(row + tc) = rv;
            }
        }
}

// ===========================================================================
// layer v4: skip-free; cond via cp.async overlapped with GEMM1; stores gated
// activations to fp16 hi/lo planes. grid (T/64=128, B), 256 thr, 3 CTAs/SM.
// smem phase1: XH[64][136] @0, XL @17408, CND fp32[128][68] @34816
// smem phase2: ABUF fp32[128][66] @0, AH[64][72] @34816, AL @44032
// ===========================================================================
#define L4_XH   0
#define L4_XL   17408
#define L4_CND  34816
#define L4_ABUF 0
#define L4_AH   34816
#define L4_AL   44032
#define L4_SMEM 69632

__global__ void __launch_bounds__(256, 3)
layer_mma4_kernel(const float* __restrict__ x_in,
                  float* __restrict__ x_out,
                  const uint4* __restrict__ wd_h, const uint4* __restrict__ wd_l,
                  const float* __restrict__ dilate_b,
                  const uint4* __restrict__ wr_h, const uint4* __restrict__ wr_l,
                  const float* __restrict__ res_b,
                  const float* __restrict__ cond_g,
                  float* __restrict__ inacts_g,
                  __half* __restrict__ act_h, __half* __restrict__ act_l,
                  int layer, int dil, int last)
{
    extern __shared__ char sb[];
    uint32_t sb_u = smem_u32(sb);
    const int tid = threadIdx.x, wid = tid >> 5, lane = tid & 31;
    const int g = lane >> 2, tg = lane & 3;
    const int t0 = blockIdx.x * 64;
    const int b  = blockIdx.y;

    // ---- phase1: cp.async cond tile; stage X halves
    {
        const float* cbase = cond_g + ((size_t)(b*LLC + layer)*128)*TT + t0;
        for (int i = tid; i < 2048; i += 256) {
            int o = i >> 4, j = i & 15;
            CP_ASYNC16(sb_u + L4_CND + o*272 + j*16, cbase + (size_t)o*TT + j*4);
        }
        CP_COMMIT();

        __half* XH = (__half*)(sb + L4_XH);
        __half* XL = (__half*)(sb + L4_XL);
        const float* xb = x_in + (size_t)b * RRC * TT;
        for (int e = tid; e < 8192; e += 256) {
            int t = e & 63, ks = e >> 6;
            float v;
            if (ks < 64) {
                int tp = t0 + t - dil;
                v = (tp >= 0) ? xb[ks*TT + tp] : 0.f;
            } else {
                v = xb[(ks - 64)*TT + t0 + t];
            }
            __half h, lo; split2(v, h, lo);
            XH[t*136 + ks] = h; XL[t*136 + ks] = lo;
        }
    }
    __syncthreads();

    const int mi = wid >> 1, ni = wid & 1;
    const int m0 = mi * 32, n0 = ni * 32;

    // ---- GEMM1: ia[128 o][64 t] = Wd @ Xcat (K=128), 3-pass
    float acc[2][4][4] = {};
    {
        const uint4* ph = wd_h + (size_t)layer * 2048;
        const uint4* pl = wd_l + (size_t)layer * 2048;
        for (int ks = 0; ks < 8; ks++) {
            uint4 A0h = ph[((mi*2    )*8 + ks)*32 + lane];
            uint4 A1h = ph[((mi*2 + 1)*8 + ks)*32 + lane];
            uint4 A0l = pl[((mi*2    )*8 + ks)*32 + lane];
            uint4 A1l = pl[((mi*2 + 1)*8 + ks)*32 + lane];
            #pragma unroll
            for (int p = 0; p < 2; p++) {
                uint32_t bh[4], bl[4];
                ldB(bh, sb, L4_XH, 136, n0 + p*16, ks*16, lane);
                ldB(bl, sb, L4_XL, 136, n0 + p*16, ks*16, lane);
                #pragma unroll
                for (int q = 0; q < 2; q++) {
                    int nt = p*2 + q;
                    mma16816(acc[0][nt], (const uint32_t*)&A0h, &bh[q*2]);
                    mma16816(acc[0][nt], (const uint32_t*)&A0h, &bl[q*2]);
                    mma16816(acc[0][nt], (const uint32_t*)&A0l, &bh[q*2]);
                    mma16816(acc[1][nt], (const uint32_t*)&A1h, &bh[q*2]);
                    mma16816(acc[1][nt], (const uint32_t*)&A1h, &bl[q*2]);
                    mma16816(acc[1][nt], (const uint32_t*)&A1l, &bh[q*2]);
                }
            }
        }
    }
    CP_WAIT0();
    __syncthreads();   // X reads done; CND landed

    // ---- epilogue1: ia -> gmem in_acts; a = ia + cond(smem) -> abuf
    {
        float* abuf = (float*)(sb + L4_ABUF);
        const float* CND = (const float*)(sb + L4_CND);
        #pragma unroll
        for (int mt = 0; mt < 2; mt++)
            #pragma unroll
            for (int r = 0; r < 2; r++) {
                int o = m0 + mt*16 + r*8 + g;
                float bias = dilate_b[layer*128 + o];
                float* iap = inacts_g + ((size_t)(b*LLC + layer)*128 + o)*TT + t0;
                float* ab = abuf + o*66;
                const float* cp = CND + o*68;
                #pragma unroll
                for (int nt = 0; nt < 4; nt++) {
                    int tc = n0 + nt*8 + 2*tg;
                    float ia0 = acc[mt][nt][r*2+0] + bias;
                    float ia1 = acc[mt][nt][r*2+1] + bias;
                    *(float2*)(iap + tc) = make_float2(ia0, ia1);
                    float2 cv = *(const float2*)(cp + tc);
                    *(float2*)(ab + tc) = make_float2(ia0 + cv.x, ia1 + cv.y);
                }
            }
    }
    __syncthreads();

    // ---- gated activation -> AH/AL (aliases CND; CND dead)
    {
        float* abuf = (float*)(sb + L4_ABUF);
        __half* AH = (__half*)(sb + L4_AH);
        __half* AL = (__half*)(sb + L4_AL);
        for (int e = tid; e < 4096; e += 256) {
            int t = e & 63, kk = e >> 6;
            float a0 = abuf[kk*66 + t];
            float a1 = abuf[(kk + 64)*66 + t];
            float act = tanhf(a0) * (1.f / (1.f + __expf(-a1)));
            __half h, lo; split2(act, h, lo);
            AH[t*72 + kk] = h; AL[t*72 + kk] = lo;
        }
    }
    __syncthreads();

    // ---- store act planes (consumed by skiphead)
    {
        uint4* gh = (uint4*)(act_h + ((size_t)(layer*BB + b)*TT + t0)*64);
        uint4* gl = (uint4*)(act_l + ((size_t)(layer*BB + b)*TT + t0)*64);
        for (int i = tid; i < 512; i += 256) {
            int t = i >> 3, j = i & 7;
            gh[t*8 + j] = *(const uint4*)(sb + L4_AH + t*144 + j*16);
            gl[t*8 + j] = *(const uint4*)(sb + L4_AL + t*144 + j*16);
        }
    }

    // ---- GEMM3: res (M=64, K=64), 3-pass; residual x update
    if (!last) {
        const int mi3 = wid >> 2, ni3 = wid & 3;
        const int m0r = mi3 * 32, n0r = ni3 * 16;
        const uint4* ph = wr_h + (size_t)layer * 512;
        const uint4* pl = wr_l + (size_t)layer * 512;
        float acc3[2][2][4] = {};
        for (int ks = 0; ks < 4; ks++) {
            uint4 A0h = ph[((mi3*2    )*4 + ks)*32 + lane];
            uint4 A1h = ph[((mi3*2 + 1)*4 + ks)*32 + lane];
            uint4 A0l = pl[((mi3*2    )*4 + ks)*32 + lane];
            uint4 A1l = pl[((mi3*2 + 1)*4 + ks)*32 + lane];
            uint32_t bh[4], bl[4];
            ldB(bh, sb, L4_AH, 72, n0r, ks*16, lane);
            ldB(bl, sb, L4_AL, 72, n0r, ks*16, lane);
            #pragma unroll
            for (int q = 0; q < 2; q++) {
                mma16816(acc3[0][q], (const uint32_t*)&A0h, &bh[q*2]);
                mma16816(acc3[0][q], (const uint32_t*)&A0h, &bl[q*2]);
                mma16816(acc3[0][q], (const uint32_t*)&A0l, &bh[q*2]);
                mma16816(acc3[1][q], (const uint32_t*)&A1h, &bh[q*2]);
                mma16816(acc3[1][q], (const uint32_t*)&A1h, &bl[q*2]);
                mma16816(acc3[1][q], (const uint32_t*)&A1l, &bh[q*2]);
            }
        }
        #pragma unroll
        for (int mt = 0; mt < 2; mt++)
            #pragma unroll
            for (int r = 0; r < 2; r++) {
                int o = m0r + mt*16 + r*8 + g;
                float rb = res_b[layer*RRC + o];
                const float* xi = x_in  + ((size_t)b*RRC + o)*TT + t0;
                float*       xo = x_out + ((size_t)b*RRC + o)*TT + t0;
                #pragma unroll
                for (int nt = 0; nt < 2; nt++) {
                    int tc = n0r + nt*8 + 2*tg;
                    float2 xv = *(const float2*)(xi + tc);
                    float2 rv;
                    rv.x = (acc3[mt][nt][r*2+0] + rb + xv.x) * SQRT_HALF;
                    rv.y = (acc3[mt][nt][r*2+1] + rb + xv.y) * SQRT_HALF;
                    *(float2*)(xo + tc) = rv;
                }
            }
    }
}

// ===========================================================================
// skiphead v2: skip accumulated over pre-stored act planes (cp.async
// double-buffered), then fused head. grid (T/64=128, B), 256 threads.
// smem: two buffers of (AH[64][72], AL[64][72]) = 2*18432; head H aliases @0.
// ===========================================================================
#define TB_SZ  18432
#define T2_SMEM 36864

__global__ void __launch_bounds__(256, 2)
skiphead2_kernel(const __half* __restrict__ act_h, const __half* __restrict__ act_l,
                 const uint4* __restrict__ ws_h, const uint4* __restrict__ ws_l,
                 const float* __restrict__ skip_b,
                 const uint4* __restrict__ wo_h, const uint4* __restrict__ we_h,
                 float* __restrict__ out)
{
    extern __shared__ char sb[];
    uint32_t sb_u = smem_u32(sb);
    const int tid = threadIdx.x, wid = tid >> 5, lane = tid & 31;
    const int g = lane >> 2, tg = lane & 3;
    const int t0 = blockIdx.x * 64;
    const int b  = blockIdx.y;

    float acc[2][8][4] = {};   // skip acc: o = wid*32 + mt*16 + r*8 + g

    auto stage = [&](int l, int buf) {
        const uint4* gh = (const uint4*)(act_h + ((size_t)(l*BB + b)*TT + t0)*64);
        const uint4* gl = (const uint4*)(act_l + ((size_t)(l*BB + b)*TT + t0)*64);
        uint32_t dh = sb_u + buf*TB_SZ;
        uint32_t dl = dh + 9216;
        for (int i = tid; i < 512; i += 256) {
            int t = i >> 3, j = i & 7;
            CP_ASYNC16(dh + t*144 + j*16, gh + t*8 + j);
            CP_ASYNC16(dl + t*144 + j*16, gl + t*8 + j);
        }
        CP_COMMIT();
    };

    stage(0, 0);
    CP_WAIT0();
    __syncthreads();

    for (int l = 0; l < LLC; l++) {
        int cur = l & 1;
        if (l + 1 < LLC) stage(l + 1, cur ^ 1);

        int offH = cur*TB_SZ, offL = offH + 9216;
        const uint4* ph = ws_h + (size_t)l * 2048;
        const uint4* pl = ws_l + (size_t)l * 2048;
        for (int ks = 0; ks < 4; ks++) {
            uint4 A0h = ph[((wid*2    )*4 + ks)*32 + lane];
            uint4 A1h = ph[((wid*2 + 1)*4 + ks)*32 + lane];
            uint4 A0l = pl[((wid*2    )*4 + ks)*32 + lane];
            uint4 A1l = pl[((wid*2 + 1)*4 + ks)*32 + lane];
            #pragma unroll
            for (int p = 0; p < 4; p++) {
                uint32_t bh[4], bl[4];
                ldB(bh, sb, offH, 72, p*16, ks*16, lane);
                ldB(bl, sb, offL, 72, p*16, ks*16, lane);
                #pragma unroll
                for (int q = 0; q < 2; q++) {
                    int nt = p*2 + q;
                    mma16816(acc[0][nt], (const uint32_t*)&A0h, &bh[q*2]);
                    mma16816(acc[0][nt], (const uint32_t*)&A0h, &bl[q*2]);
                    mma16816(acc[0][nt], (const uint32_t*)&A0l, &bh[q*2]);
                    mma16816(acc[1][nt], (const uint32_t*)&A1h, &bh[q*2]);
                    mma16816(acc[1][nt], (const uint32_t*)&A1h, &bl[q*2]);
                    mma16816(acc[1][nt], (const uint32_t*)&A1l, &bh[q*2]);
                }
            }
        }
        if (l + 1 < LLC) CP_WAIT0();
        __syncthreads();
    }

    // skip bias sum + relu -> H fp16 [t][o:256] (aliases buffers)
    {
        __half* H = (__half*)sb;
        #pragma unroll
        for (int mt = 0; mt < 2; mt++)
            #pragma unroll
            for (int r = 0; r < 2; r++) {
                int o = wid*32 + mt*16 + r*8 + g;
                float bs = 0.f;
                #pragma unroll
                for (int l = 0; l < LLC; l++) bs += skip_b[l*SSC + o];
                #pragma unroll
                for (int nt = 0; nt < 8; nt++) {
                    int t = nt*8 + tg*2;
                    H[t*264 + o]     = __float2half_rn(fmaxf(acc[mt][nt][r*2+0] + bs, 0.f));
                    H[(t+1)*264 + o] = __float2half_rn(fmaxf(acc[mt][nt][r*2+1] + bs, 0.f));
                }
            }
    }
    __syncthreads();

    // head GEMM A: h2 = relu(Wout @ h) (single-pass)
    float acc2[2][8][4] = {};
    for (int ks = 0; ks < 16; ks++) {
        uint4 A0 = wo_h[((wid*2    )*16 + ks)*32 + lane];
        uint4 A1 = wo_h[((wid*2 + 1)*16 + ks)*32 + lane];
        #pragma unroll
        for (int p = 0; p < 4; p++) {
            uint32_t bh[4];
            ldB(bh, sb, 0, 264, p*16, ks*16, lane);
            #pragma unroll
            for (int q = 0; q < 2; q++) {
                int nt = p*2 + q;
                mma16816(acc2[0][nt], (const uint32_t*)&A0, &bh[q*2]);
                mma16816(acc2[1][nt], (const uint32_t*)&A1, &bh[q*2]);
            }
        }
    }
    __syncthreads();
    {
        __half* H = (__half*)sb;
        #pragma unroll
        for (int mt = 0; mt < 2; mt++)
            #pragma unroll
            for (int r = 0; r < 2; r++) {
                int o = wid*32 + mt*16 + r*8 + g;
                #pragma unroll
                for (int nt = 0; nt < 8; nt++) {
                    int t = nt*8 + tg*2;
                    H[t*264 + o]     = __float2half_rn(fmaxf(acc2[mt][nt][r*2+0], 0.f));
                    H[(t+1)*264 + o] = __float2half_rn(fmaxf(acc2[mt][nt][r*2+1], 0.f));
                }
            }
    }
    __syncthreads();

    // head GEMM B: out = Wend @ h2, shifted right by 1
    float acc3[2][8][4] = {};
    for (int ks = 0; ks < 16; ks++) {
        uint4 A0 = we_h[((wid*2    )*16 + ks)*32 + lane];
        uint4 A1 = we_h[((wid*2 + 1)*16 + ks)*32 + lane];
        #pragma unroll
        for (int p = 0; p < 4; p++) {
            uint32_t bh[4];
            ldB(bh, sb, 0, 264, p*16, ks*16, lane);
            #pragma unroll
            for (int q = 0; q < 2; q++) {
                int nt = p*2 + q;
                mma16816(acc3[0][nt], (const uint32_t*)&A0, &bh[q*2]);
                mma16816(acc3[1][nt], (const uint32_t*)&A1, &bh[q*2]);
            }
        }
    }
    #pragma unroll
    for (int mt = 0; mt < 2; mt++)
        #pragma unroll
        for (int r = 0; r < 2; r++) {
            int o = wid*32 + mt*16 + r*8 + g;
            float* op = out + ((size_t)b*256 + o)*TT;
            #pragma unroll
            for (int nt = 0; nt < 8; nt++) {
                int tc = t0 + nt*8 + 2*tg;
                if (tc + 1 < TT) op[tc + 1] = acc3[mt][nt][r*2+0];
                if (tc + 2 < TT) op[tc + 2] = acc3[mt][nt][r*2+1];
            }
        }
    if (blockIdx.x == 0) out[((size_t)b*256 + tid)*TT] = 0.f;
}

// ===========================================================================
extern "C" void kernel_launch(void* const* d_in, const int* in_sizes, int n_in,
                              void* d_out, int out_size)
{
    const float* features   = (const float*)d_in[0];
    const int*   tokens     = (const int*)  d_in[1];
    const float* embed      = (const float*)d_in[2];
    const float* cond_W     = (const float*)d_in[3];
    const float* cond_b     = (const float*)d_in[4];
    const float* dilate_W   = (const float*)d_in[5];
    const float* dilate_b   = (const float*)d_in[6];
    const float* res_W      = (const float*)d_in[7];
    const float* res_b      = (const float*)d_in[8];
    const float* skip_W     = (const float*)d_in[9];
    const float* skip_b     = (const float*)d_in[10];
    const float* conv_out_W = (const float*)d_in[11];
    const float* conv_end_W = (const float*)d_in[12];
    float* outp = (float*)d_out;

    float* out_r   = outp;
    float* inact_r = outp + INACT_OFF;
    float* cond_r  = outp + COND_OFF;

    float *x0, *x1;
    __half *ah, *al;
    uint4 *wdh, *wdl, *wsh, *wsl, *wrh, *wrl, *woh, *weh;
    cudaGetSymbolAddress((void**)&x0,  g_x0);
    cudaGetSymbolAddress((void**)&x1,  g_x1);
    cudaGetSymbolAddress((void**)&ah,  g_act_h);
    cudaGetSymbolAddress((void**)&al,  g_act_l);
    cudaGetSymbolAddress((void**)&wdh, g_wd_h);
    cudaGetSymbolAddress((void**)&wdl, g_wd_l);
    cudaGetSymbolAddress((void**)&wsh, g_ws_h);
    cudaGetSymbolAddress((void**)&wsl, g_ws_l);
    cudaGetSymbolAddress((void**)&wrh, g_wr_h);
    cudaGetSymbolAddress((void**)&wrl, g_wr_l);
    cudaGetSymbolAddress((void**)&woh, g_wo_h);
    cudaGetSymbolAddress((void**)&weh, g_we_h);

    static const int DIL[LLC] = {1,2,4,8,16,32,64,128,256,1,2,4,8,16,32,64};

    cudaFuncSetAttribute(cond_mma_kernel,   cudaFuncAttributeMaxDynamicSharedMemorySize, CO_SMEM);
    cudaFuncSetAttribute(layer_mma4_kernel, cudaFuncAttributeMaxDynamicSharedMemorySize, L4_SMEM);
    cudaFuncSetAttribute(skiphead2_kernel,  cudaFuncAttributeMaxDynamicSharedMemorySize, T2_SMEM);

    pack_dilate<<<128, 256>>>(dilate_W, wdh, wdl);
    pack_skip<<<128, 256>>>(skip_W, wsh, wsl);
    pack_res<<<30, 256>>>(res_W, wrh, wrl);
    pack_w256<<<32, 256>>>(conv_out_W, woh);
    pack_w256<<<32, 256>>>(conv_end_W, weh);

    embed_kernel<<<dim3(TT/256, BB), 256>>>(tokens, embed, x0);
    cond_mma_kernel<<<dim3(TT/128, LLC, BB), 512, CO_SMEM>>>(features, cond_W, cond_b, cond_r);

    float* xi = x0;
    float* xo = x1;
    for (int i = 0; i < LLC; i++) {
        layer_mma4_kernel<<<dim3(TT/64, BB), 256, L4_SMEM>>>(
            xi, xo, wdh, wdl, dilate_b, wrh, wrl, res_b,
            cond_r, inact_r, ah, al,
            i, DIL[i], (i == LLC-1) ? 1 : 0);
        float* t = xi; xi = xo; xo = t;
    }

    skiphead2_kernel<<<dim3(TT/64, BB), 256, T2_SMEM>>>(
        ah, al, wsh, wsl, skip_b, woh, weh, out_r);
}

// round 9
// speedup vs baseline: 1.4768x; 1.1105x over previous
#include <cuda_runtime.h>
#include <cuda_fp16.h>
#include <math.h>
#include <stdint.h>

// Problem constants
#define BB 4
#define TT 8192
#define CC 128
#define RRC 64       // residual channels
#define SSC 256      // skip channels
#define LLC 16

// Output region offsets (pytree flatten order: out, in_acts, cond)
#define OUT_SZ     (BB*256*TT)
#define INACT_OFF  (OUT_SZ)
#define INACT_SZ   (BB*LLC*128*TT)
#define COND_OFF   (INACT_OFF + INACT_SZ)

#define SQRT_HALF 0.70710678118654752440f

// Scratch (device globals; no allocation allowed)
__device__ float g_x0[BB*RRC*TT];
__device__ float g_x1[BB*RRC*TT];

// Gated activations, fp16 hi/lo planes, layout [l][b][t][64ch]
__device__ __align__(16) __half g_act_h[LLC*BB*TT*64];
__device__ __align__(16) __half g_act_l[LLC*BB*TT*64];

// Pre-packed A-operand fragments (fp16 hi/lo), mma.m16n8k16 layout.
__device__ uint4 g_wd_h[LLC*2048];
__device__ uint4 g_wd_l[LLC*2048];
__device__ uint4 g_ws_h[LLC*2048];
__device__ uint4 g_ws_l[LLC*2048];
__device__ uint4 g_wr_h[15*512];
__device__ uint4 g_wr_l[15*512];
__device__ uint4 g_wc_h[LLC*2048];  // cond_W frags (hi/lo)
__device__ uint4 g_wc_l[LLC*2048];
__device__ uint4 g_wo_h[8192];      // conv_out_W frags (hi only)
__device__ uint4 g_we_h[8192];      // conv_end_W frags (hi only)

// ===========================================================================
// helpers
// ===========================================================================
__device__ __forceinline__ uint32_t smem_u32(const void* p) {
    uint32_t a;
    asm("{ .reg .u64 t; cvta.to.shared.u64 t, %1; cvt.u32.u64 %0, t; }" : "=r"(a) : "l"(p));
    return a;
}
__device__ __forceinline__ void ldsm4(uint32_t* r, uint32_t a) {
    asm volatile("ldmatrix.sync.aligned.m8n8.x4.shared.b16 {%0,%1,%2,%3}, [%4];"
        : "=r"(r[0]), "=r"(r[1]), "=r"(r[2]), "=r"(r[3]) : "r"(a));
}
__device__ __forceinline__ void mma16816(float* d, const uint32_t* a, const uint32_t* b) {
    asm volatile(
        "mma.sync.aligned.m16n8k16.row.col.f32.f16.f16.f32 "
        "{%0,%1,%2,%3}, {%4,%5,%6,%7}, {%8,%9}, {%0,%1,%2,%3};"
        : "+f"(d[0]), "+f"(d[1]), "+f"(d[2]), "+f"(d[3])
        : "r"(a[0]), "r"(a[1]), "r"(a[2]), "r"(a[3]), "r"(b[0]), "r"(b[1]));
}
__device__ __forceinline__ void ldB(uint32_t* fr, const char* sb, int off, int stride,
                                    int n0, int k0, int lane) {
    uint32_t a = smem_u32(sb + off) +
        (uint32_t)(((n0 + ((lane >> 4) & 1) * 8 + (lane & 7)) * stride
                    + k0 + ((lane >> 3) & 1) * 8) << 1);
    ldsm4(fr, a);
}
__device__ __forceinline__ void split2(float v, __half& h, __half& l) {
    h = __float2half_rn(v);
    l = __float2half_rn(v - __half2float(h));
}
__device__ __forceinline__ uint32_t packh2(__half a, __half b) {
    __half2 h = __halves2half2(a, b);
    return *(uint32_t*)&h;
}

#define CP_ASYNC16(dst, src) \
    asm volatile("cp.async.ca.shared.global [%0], [%1], 16;" :: "r"(dst), "l"(src))
#define CP_COMMIT() asm volatile("cp.async.commit_group;" ::: "memory")
#define CP_WAIT0()  asm volatile("cp.async.wait_group 0;" ::: "memory")

// ===========================================================================
// weight pre-pack kernels
// ===========================================================================
__device__ __forceinline__ void pack8(const float* v, uint4& hi, uint4& lo) {
    __half eh[8], el[8];
    #pragma unroll
    for (int i = 0; i < 8; i++) split2(v[i], eh[i], el[i]);
    hi.x = packh2(eh[0], eh[1]); hi.y = packh2(eh[2], eh[3]);
    hi.z = packh2(eh[4], eh[5]); hi.w = packh2(eh[6], eh[7]);
    lo.x = packh2(el[0], el[1]); lo.y = packh2(el[2], el[3]);
    lo.z = packh2(el[4], el[5]); lo.w = packh2(el[6], el[7]);
}

__global__ void pack_dilate(const float* __restrict__ dilate_W,
                            uint4* __restrict__ outh, uint4* __restrict__ outl)
{
    int idx = blockIdx.x * 256 + threadIdx.x;   // 32768
    int lane = idx & 31, fi = idx >> 5;
    int ks = fi & 7, mt = (fi >> 3) & 7, l = fi >> 6;
    int r = mt*16 + (lane >> 2), cb = ks*16 + (lane & 3)*2;
    int dr[8] = {0,0,8,8,0,0,8,8};
    int dc[8] = {0,1,0,1,8,9,8,9};
    float v[8];
    #pragma unroll
    for (int i = 0; i < 8; i++) {
        int row = r + dr[i], col = cb + dc[i];
        v[i] = (col < 64)
            ? dilate_W[((l*128 + row)*64 + col)*2 + 0]
            : dilate_W[((l*128 + row)*64 + (col - 64))*2 + 1];
    }
    uint4 hi, lo; pack8(v, hi, lo);
    outh[idx] = hi; outl[idx] = lo;
}

// cond_W [2048][128] -> per-layer frags, layout identical to dilate
__global__ void pack_cond(const float* __restrict__ cond_W,
                          uint4* __restrict__ outh, uint4* __restrict__ outl)
{
    int idx = blockIdx.x * 256 + threadIdx.x;   // 32768
    int lane = idx & 31, fi = idx >> 5;
    int ks = fi & 7, mt = (fi >> 3) & 7, l = fi >> 6;
    int r = mt*16 + (lane >> 2), cb = ks*16 + (lane & 3)*2;
    int dr[8] = {0,0,8,8,0,0,8,8};
    int dc[8] = {0,1,0,1,8,9,8,9};
    float v[8];
    #pragma unroll
    for (int i = 0; i < 8; i++)
        v[i] = cond_W[((size_t)(l*128 + r + dr[i]))*CC + cb + dc[i]];
    uint4 hi, lo; pack8(v, hi, lo);
    outh[idx] = hi; outl[idx] = lo;
}

__global__ void pack_skip(const float* __restrict__ skip_W,
                          uint4* __restrict__ outh, uint4* __restrict__ outl)
{
    int idx = blockIdx.x * 256 + threadIdx.x;   // 32768
    int lane = idx & 31, fi = idx >> 5;
    int ks = fi & 3, mt = (fi >> 2) & 15, l = fi >> 6;
    int r = mt*16 + (lane >> 2), cb = ks*16 + (lane & 3)*2;
    int dr[8] = {0,0,8,8,0,0,8,8};
    int dc[8] = {0,1,0,1,8,9,8,9};
    float v[8];
    #pragma unroll
    for (int i = 0; i < 8; i++)
        v[i] = skip_W[((size_t)l*256 + r + dr[i])*64 + cb + dc[i]];
    uint4 hi, lo; pack8(v, hi, lo);
    outh[idx] = hi; outl[idx] = lo;
}

__global__ void pack_res(const float* __restrict__ res_W,
                         uint4* __restrict__ outh, uint4* __restrict__ outl)
{
    int idx = blockIdx.x * 256 + threadIdx.x;
    if (idx >= 7680) return;
    int lane = idx & 31, fi = idx >> 5;
    int ks = fi & 3, mt = (fi >> 2) & 3, l = fi >> 4;
    int r = mt*16 + (lane >> 2), cb = ks*16 + (lane & 3)*2;
    int dr[8] = {0,0,8,8,0,0,8,8};
    int dc[8] = {0,1,0,1,8,9,8,9};
    float v[8];
    #pragma unroll
    for (int i = 0; i < 8; i++)
        v[i] = res_W[((size_t)l*64 + r + dr[i])*64 + cb + dc[i]];
    uint4 hi, lo; pack8(v, hi, lo);
    outh[idx] = hi; outl[idx] = lo;
}

__global__ void pack_w256(const float* __restrict__ W, uint4* __restrict__ outh)
{
    int idx = blockIdx.x * 256 + threadIdx.x;
    int lane = idx & 31, fi = idx >> 5;
    int ks = fi & 15, mt = fi >> 4;
    int r = mt*16 + (lane >> 2), cb = ks*16 + (lane & 3)*2;
    int dr[8] = {0,0,8,8,0,0,8,8};
    int dc[8] = {0,1,0,1,8,9,8,9};
    __half eh[8];
    #pragma unroll
    for (int i = 0; i < 8; i++)
        eh[i] = __float2half_rn(W[(r + dr[i])*256 + cb + dc[i]]);
    uint4 hi;
    hi.x = packh2(eh[0], eh[1]); hi.y = packh2(eh[2], eh[3]);
    hi.z = packh2(eh[4], eh[5]); hi.w = packh2(eh[6], eh[7]);
    outh[idx] = hi;
}

// ===========================================================================
// embed
// ===========================================================================
__global__ void embed_kernel(const int* __restrict__ tokens,
                             const float* __restrict__ embed,
                             float* __restrict__ x0)
{
    __shared__ int tok[256];
    const int t0 = blockIdx.x * 256;
    const int b  = blockIdx.y;
    tok[threadIdx.x] = tokens[b*TT + t0 + threadIdx.x];
    __syncthreads();
    const int v = tok[threadIdx.x];
    #pragma unroll 4
    for (int r = 0; r < RRC; r++)
        x0[(b*RRC + r)*TT + t0 + threadIdx.x] = embed[v*RRC + r];
}

// ===========================================================================
// cond v2: layer-style GEMM. 256 thr, t-tile 64, one layer per blockIdx.y.
// A from pre-packed frags (gmem), B = features staged hi/lo in smem.
// grid (T/64=128, 16, B), smem 34816 -> 3 CTAs/SM.
// ===========================================================================
#define C2_FH 0
#define C2_FL 17408
#define C2_SMEM 34816

__global__ void __launch_bounds__(256, 3)
cond_mma2_kernel(const float* __restrict__ features,
                 const uint4* __restrict__ wc_h, const uint4* __restrict__ wc_l,
                 const float* __restrict__ cond_b,
                 float* __restrict__ cond_out)
{
    extern __shared__ char sb[];
    const int tid = threadIdx.x, wid = tid >> 5, lane = tid & 31;
    const int g = lane >> 2, tg = lane & 3;
    const int t0 = blockIdx.x * 64;
    const int l  = blockIdx.y;
    const int b  = blockIdx.z;

    // stage features tile [t:64][k:128] hi/lo
    {
        __half* FH = (__half*)(sb + C2_FH);
        __half* FL = (__half*)(sb + C2_FL);
        for (int e = tid; e < 8192; e += 256) {
            int t = e & 63, k = e >> 6;
            float v = features[((size_t)b*CC + k)*TT + t0 + t];
            __half h, lo; split2(v, h, lo);
            FH[t*136 + k] = h; FL[t*136 + k] = lo;
        }
    }
    __syncthreads();

    const int mi = wid >> 1, ni = wid & 1;
    const int m0 = mi * 32, n0 = ni * 32;

    float acc[2][4][4] = {};
    {
        const uint4* ph = wc_h + (size_t)l * 2048;
        const uint4* pl = wc_l + (size_t)l * 2048;
        for (int ks = 0; ks < 8; ks++) {
            uint4 A0h = ph[((mi*2    )*8 + ks)*32 + lane];
            uint4 A1h = ph[((mi*2 + 1)*8 + ks)*32 + lane];
            uint4 A0l = pl[((mi*2    )*8 + ks)*32 + lane];
            uint4 A1l = pl[((mi*2 + 1)*8 + ks)*32 + lane];
            #pragma unroll
            for (int p = 0; p < 2; p++) {
                uint32_t bh[4], bl[4];
                ldB(bh, sb, C2_FH, 136, n0 + p*16, ks*16, lane);
                ldB(bl, sb, C2_FL, 136, n0 + p*16, ks*16, lane);
                #pragma unroll
                for (int q = 0; q < 2; q++) {
                    int nt = p*2 + q;
                    mma16816(acc[0][nt], (const uint32_t*)&A0h, &bh[q*2]);
                    mma16816(acc[0][nt], (const uint32_t*)&A0h, &bl[q*2]);
                    mma16816(acc[0][nt], (const uint32_t*)&A0l, &bh[q*2]);
                    mma16816(acc[1][nt], (const uint32_t*)&A1h, &bh[q*2]);
                    mma16816(acc[1][nt], (const uint32_t*)&A1h, &bl[q*2]);
                    mma16816(acc[1][nt], (const uint32_t*)&A1l, &bh[q*2]);
                }
            }
        }
    }

    #pragma unroll
    for (int mt = 0; mt < 2; mt++)
        #pragma unroll
        for (int r = 0; r < 2; r++) {
            int o = m0 + mt*16 + r*8 + g;
            float bias = cond_b[l*128 + o];
            float* row = cond_out + ((size_t)(b*LLC + l)*128 + o)*TT + t0;
            #pragma unroll
            for (int nt = 0; nt < 4; nt++) {
                int tc = n0 + nt*8 + 2*tg;
                float2 rv = make_float2(acc[mt][nt][r*2+0] + bias,
                                        acc[mt][nt][r*2+1] + bias);
                *(float2*)(row + tc) = rv;
            }
        }
}

// ===========================================================================
// layer v4 (unchanged from R8): skip-free; cond via cp.async under GEMM1;
// stores gated activations to fp16 hi/lo planes. grid (T/64=128, B).
// ===========================================================================
#define L4_XH   0
#define L4_XL   17408
#define L4_CND  34816
#define L4_ABUF 0
#define L4_AH   34816
#define L4_AL   44032
#define L4_SMEM 69632

__global__ void __launch_bounds__(256, 3)
layer_mma4_kernel(const float* __restrict__ x_in,
                  float* __restrict__ x_out,
                  const uint4* __restrict__ wd_h, const uint4* __restrict__ wd_l,
                  const float* __restrict__ dilate_b,
                  const uint4* __restrict__ wr_h, const uint4* __restrict__ wr_l,
                  const float* __restrict__ res_b,
                  const float* __restrict__ cond_g,
                  float* __restrict__ inacts_g,
                  __half* __restrict__ act_h, __half* __restrict__ act_l,
                  int layer, int dil, int last)
{
    extern __shared__ char sb[];
    uint32_t sb_u = smem_u32(sb);
    const int tid = threadIdx.x, wid = tid >> 5, lane = tid & 31;
    const int g = lane >> 2, tg = lane & 3;
    const int t0 = blockIdx.x * 64;
    const int b  = blockIdx.y;

    // ---- phase1: cp.async cond tile; stage X halves
    {
        const float* cbase = cond_g + ((size_t)(b*LLC + layer)*128)*TT + t0;
        for (int i = tid; i < 2048; i += 256) {
            int o = i >> 4, j = i & 15;
            CP_ASYNC16(sb_u + L4_CND + o*272 + j*16, cbase + (size_t)o*TT + j*4);
        }
        CP_COMMIT();

        __half* XH = (__half*)(sb + L4_XH);
        __half* XL = (__half*)(sb + L4_XL);
        const float* xb = x_in + (size_t)b * RRC * TT;
        for (int e = tid; e < 8192; e += 256) {
            int t = e & 63, ks = e >> 6;
            float v;
            if (ks < 64) {
                int tp = t0 + t - dil;
                v = (tp >= 0) ? xb[ks*TT + tp] : 0.f;
            } else {
                v = xb[(ks - 64)*TT + t0 + t];
            }
            __half h, lo; split2(v, h, lo);
            XH[t*136 + ks] = h; XL[t*136 + ks] = lo;
        }
    }
    __syncthreads();

    const int mi = wid >> 1, ni = wid & 1;
    const int m0 = mi * 32, n0 = ni * 32;

    // ---- GEMM1: ia[128 o][64 t] = Wd @ Xcat (K=128), 3-pass
    float acc[2][4][4] = {};
    {
        const uint4* ph = wd_h + (size_t)layer * 2048;
        const uint4* pl = wd_l + (size_t)layer * 2048;
        for (int ks = 0; ks < 8; ks++) {
            uint4 A0h = ph[((mi*2    )*8 + ks)*32 + lane];
            uint4 A1h = ph[((mi*2 + 1)*8 + ks)*32 + lane];
            uint4 A0l = pl[((mi*2    )*8 + ks)*32 + lane];
            uint4 A1l = pl[((mi*2 + 1)*8 + ks)*32 + lane];
            #pragma unroll
            for (int p = 0; p < 2; p++) {
                uint32_t bh[4], bl[4];
                ldB(bh, sb, L4_XH, 136, n0 + p*16, ks*16, lane);
                ldB(bl, sb, L4_XL, 136, n0 + p*16, ks*16, lane);
                #pragma unroll
                for (int q = 0; q < 2; q++) {
                    int nt = p*2 + q;
                    mma16816(acc[0][nt], (const uint32_t*)&A0h, &bh[q*2]);
                    mma16816(acc[0][nt], (const uint32_t*)&A0h, &bl[q*2]);
                    mma16816(acc[0][nt], (const uint32_t*)&A0l, &bh[q*2]);
                    mma16816(acc[1][nt], (const uint32_t*)&A1h, &bh[q*2]);
                    mma16816(acc[1][nt], (const uint32_t*)&A1h, &bl[q*2]);
                    mma16816(acc[1][nt], (const uint32_t*)&A1l, &bh[q*2]);
                }
            }
        }
    }
    CP_WAIT0();
    __syncthreads();   // X reads done; CND landed

    // ---- epilogue1: ia -> gmem in_acts; a = ia + cond(smem) -> abuf
    {
        float* abuf = (float*)(sb + L4_ABUF);
        const float* CND = (const float*)(sb + L4_CND);
        #pragma unroll
        for (int mt = 0; mt < 2; mt++)
            #pragma unroll
            for (int r = 0; r < 2; r++) {
                int o = m0 + mt*16 + r*8 + g;
                float bias = dilate_b[layer*128 + o];
                float* iap = inacts_g + ((size_t)(b*LLC + layer)*128 + o)*TT + t0;
                float* ab = abuf + o*66;
                const float* cp = CND + o*68;
                #pragma unroll
                for (int nt = 0; nt < 4; nt++) {
                    int tc = n0 + nt*8 + 2*tg;
                    float ia0 = acc[mt][nt][r*2+0] + bias;
                    float ia1 = acc[mt][nt][r*2+1] + bias;
                    *(float2*)(iap + tc) = make_float2(ia0, ia1);
                    float2 cv = *(const float2*)(cp + tc);
                    *(float2*)(ab + tc) = make_float2(ia0 + cv.x, ia1 + cv.y);
                }
            }
    }
    __syncthreads();

    // ---- gated activation -> AH/AL (aliases CND; CND dead)
    {
        float* abuf = (float*)(sb + L4_ABUF);
        __half* AH = (__half*)(sb + L4_AH);
        __half* AL = (__half*)(sb + L4_AL);
        for (int e = tid; e < 4096; e += 256) {
            int t = e & 63, kk = e >> 6;
            float a0 = abuf[kk*66 + t];
            float a1 = abuf[(kk + 64)*66 + t];
            float act = tanhf(a0) * (1.f / (1.f + __expf(-a1)));
            __half h, lo; split2(act, h, lo);
            AH[t*72 + kk] = h; AL[t*72 + kk] = lo;
        }
    }
    __syncthreads();

    // ---- store act planes (consumed by skiphead)
    {
        uint4* gh = (uint4*)(act_h + ((size_t)(layer*BB + b)*TT + t0)*64);
        uint4* gl = (uint4*)(act_l + ((size_t)(layer*BB + b)*TT + t0)*64);
        for (int i = tid; i < 512; i += 256) {
            int t = i >> 3, j = i & 7;
            gh[t*8 + j] = *(const uint4*)(sb + L4_AH + t*144 + j*16);
            gl[t*8 + j] = *(const uint4*)(sb + L4_AL + t*144 + j*16);
        }
    }

    // ---- GEMM3: res (M=64, K=64), 3-pass; residual x update
    if (!last) {
        const int mi3 = wid >> 2, ni3 = wid & 3;
        const int m0r = mi3 * 32, n0r = ni3 * 16;
        const uint4* ph = wr_h + (size_t)layer * 512;
        const uint4* pl = wr_l + (size_t)layer * 512;
        float acc3[2][2][4] = {};
        for (int ks = 0; ks < 4; ks++) {
            uint4 A0h = ph[((mi3*2    )*4 + ks)*32 + lane];
            uint4 A1h = ph[((mi3*2 + 1)*4 + ks)*32 + lane];
            uint4 A0l = pl[((mi3*2    )*4 + ks)*32 + lane];
            uint4 A1l = pl[((mi3*2 + 1)*4 + ks)*32 + lane];
            uint32_t bh[4], bl[4];
            ldB(bh, sb, L4_AH, 72, n0r, ks*16, lane);
            ldB(bl, sb, L4_AL, 72, n0r, ks*16, lane);
            #pragma unroll
            for (int q = 0; q < 2; q++) {
                mma16816(acc3[0][q], (const uint32_t*)&A0h, &bh[q*2]);
                mma16816(acc3[0][q], (const uint32_t*)&A0h, &bl[q*2]);
                mma16816(acc3[0][q], (const uint32_t*)&A0l, &bh[q*2]);
                mma16816(acc3[1][q], (const uint32_t*)&A1h, &bh[q*2]);
                mma16816(acc3[1][q], (const uint32_t*)&A1h, &bl[q*2]);
                mma16816(acc3[1][q], (const uint32_t*)&A1l, &bh[q*2]);
            }
        }
        #pragma unroll
        for (int mt = 0; mt < 2; mt++)
            #pragma unroll
            for (int r = 0; r < 2; r++) {
                int o = m0r + mt*16 + r*8 + g;
                float rb = res_b[layer*RRC + o];
                const float* xi = x_in  + ((size_t)b*RRC + o)*TT + t0;
                float*       xo = x_out + ((size_t)b*RRC + o)*TT + t0;
                #pragma unroll
                for (int nt = 0; nt < 2; nt++) {
                    int tc = n0r + nt*8 + 2*tg;
                    float2 xv = *(const float2*)(xi + tc);
                    float2 rv;
                    rv.x = (acc3[mt][nt][r*2+0] + rb + xv.x) * SQRT_HALF;
                    rv.y = (acc3[mt][nt][r*2+1] + rb + xv.y) * SQRT_HALF;
                    *(float2*)(xo + tc) = rv;
                }
            }
    }
}

// ===========================================================================
// skiphead v2 (unchanged from R8)
// ===========================================================================
#define TB_SZ  18432
#define T2_SMEM 36864

__global__ void __launch_bounds__(256, 2)
skiphead2_kernel(const __half* __restrict__ act_h, const __half* __restrict__ act_l,
                 const uint4* __restrict__ ws_h, const uint4* __restrict__ ws_l,
                 const float* __restrict__ skip_b,
                 const uint4* __restrict__ wo_h, const uint4* __restrict__ we_h,
                 float* __restrict__ out)
{
    extern __shared__ char sb[];
    uint32_t sb_u = smem_u32(sb);
    const int tid = threadIdx.x, wid = tid >> 5, lane = tid & 31;
    const int g = lane >> 2, tg = lane & 3;
    const int t0 = blockIdx.x * 64;
    const int b  = blockIdx.y;

    float acc[2][8][4] = {};   // skip acc: o = wid*32 + mt*16 + r*8 + g

    auto stage = [&](int l, int buf) {
        const uint4* gh = (const uint4*)(act_h + ((size_t)(l*BB + b)*TT + t0)*64);
        const uint4* gl = (const uint4*)(act_l + ((size_t)(l*BB + b)*TT + t0)*64);
        uint32_t dh = sb_u + buf*TB_SZ;
        uint32_t dl = dh + 9216;
        for (int i = tid; i < 512; i += 256) {
            int t = i >> 3, j = i & 7;
            CP_ASYNC16(dh + t*144 + j*16, gh + t*8 + j);
            CP_ASYNC16(dl + t*144 + j*16, gl + t*8 + j);
        }
        CP_COMMIT();
    };

    stage(0, 0);
    CP_WAIT0();
    __syncthreads();

    for (int l = 0; l < LLC; l++) {
        int cur = l & 1;
        if (l + 1 < LLC) stage(l + 1, cur ^ 1);

        int offH = cur*TB_SZ, offL = offH + 9216;
        const uint4* ph = ws_h + (size_t)l * 2048;
        const uint4* pl = ws_l + (size_t)l * 2048;
        for (int ks = 0; ks < 4; ks++) {
            uint4 A0h = ph[((wid*2    )*4 + ks)*32 + lane];
            uint4 A1h = ph[((wid*2 + 1)*4 + ks)*32 + lane];
            uint4 A0l = pl[((wid*2    )*4 + ks)*32 + lane];
            uint4 A1l = pl[((wid*2 + 1)*4 + ks)*32 + lane];
            #pragma unroll
            for (int p = 0; p < 4; p++) {
                uint32_t bh[4], bl[4];
                ldB(bh, sb, offH, 72, p*16, ks*16, lane);
                ldB(bl, sb, offL, 72, p*16, ks*16, lane);
                #pragma unroll
                for (int q = 0; q < 2; q++) {
                    int nt = p*2 + q;
                    mma16816(acc[0][nt], (const uint32_t*)&A0h, &bh[q*2]);
                    mma16816(acc[0][nt], (const uint32_t*)&A0h, &bl[q*2]);
                    mma16816(acc[0][nt], (const uint32_t*)&A0l, &bh[q*2]);
                    mma16816(acc[1][nt], (const uint32_t*)&A1h, &bh[q*2]);
                    mma16816(acc[1][nt], (const uint32_t*)&A1h, &bl[q*2]);
                    mma16816(acc[1][nt], (const uint32_t*)&A1l, &bh[q*2]);
                }
            }
        }
        if (l + 1 < LLC) CP_WAIT0();
        __syncthreads();
    }

    // skip bias sum + relu -> H fp16 [t][o:256] (aliases buffers)
    {
        __half* H = (__half*)sb;
        #pragma unroll
        for (int mt = 0; mt < 2; mt++)
            #pragma unroll
            for (int r = 0; r < 2; r++) {
                int o = wid*32 + mt*16 + r*8 + g;
                float bs = 0.f;
                #pragma unroll
                for (int l = 0; l < LLC; l++) bs += skip_b[l*SSC + o];
                #pragma unroll
                for (int nt = 0; nt < 8; nt++) {
                    int t = nt*8 + tg*2;
                    H[t*264 + o]     = __float2half_rn(fmaxf(acc[mt][nt][r*2+0] + bs, 0.f));
                    H[(t+1)*264 + o] = __float2half_rn(fmaxf(acc[mt][nt][r*2+1] + bs, 0.f));
                }
            }
    }
    __syncthreads();

    // head GEMM A: h2 = relu(Wout @ h) (single-pass)
    float acc2[2][8][4] = {};
    for (int ks = 0; ks < 16; ks++) {
        uint4 A0 = wo_h[((wid*2    )*16 + ks)*32 + lane];
        uint4 A1 = wo_h[((wid*2 + 1)*16 + ks)*32 + lane];
        #pragma unroll
        for (int p = 0; p < 4; p++) {
            uint32_t bh[4];
            ldB(bh, sb, 0, 264, p*16, ks*16, lane);
            #pragma unroll
            for (int q = 0; q < 2; q++) {
                int nt = p*2 + q;
                mma16816(acc2[0][nt], (const uint32_t*)&A0, &bh[q*2]);
                mma16816(acc2[1][nt], (const uint32_t*)&A1, &bh[q*2]);
            }
        }
    }
    __syncthreads();
    {
        __half* H = (__half*)sb;
        #pragma unroll
        for (int mt = 0; mt < 2; mt++)
            #pragma unroll
            for (int r = 0; r < 2; r++) {
                int o = wid*32 + mt*16 + r*8 + g;
                #pragma unroll
                for (int nt = 0; nt < 8; nt++) {
                    int t = nt*8 + tg*2;
                    H[t*264 + o]     = __float2half_rn(fmaxf(acc2[mt][nt][r*2+0], 0.f));
                    H[(t+1)*264 + o] = __float2half_rn(fmaxf(acc2[mt][nt][r*2+1], 0.f));
                }
            }
    }
    __syncthreads();

    // head GEMM B: out = Wend @ h2, shifted right by 1
    float acc3[2][8][4] = {};
    for (int ks = 0; ks < 16; ks++) {
        uint4 A0 = we_h[((wid*2    )*16 + ks)*32 + lane];
        uint4 A1 = we_h[((wid*2 + 1)*16 + ks)*32 + lane];
        #pragma unroll
        for (int p = 0; p < 4; p++) {
            uint32_t bh[4];
            ldB(bh, sb, 0, 264, p*16, ks*16, lane);
            #pragma unroll
            for (int q = 0; q < 2; q++) {
                int nt = p*2 + q;
                mma16816(acc3[0][nt], (const uint32_t*)&A0, &bh[q*2]);
                mma16816(acc3[1][nt], (const uint32_t*)&A1, &bh[q*2]);
            }
        }
    }
    #pragma unroll
    for (int mt = 0; mt < 2; mt++)
        #pragma unroll
        for (int r = 0; r < 2; r++) {
            int o = wid*32 + mt*16 + r*8 + g;
            float* op = out + ((size_t)b*256 + o)*TT;
            #pragma unroll
            for (int nt = 0; nt < 8; nt++) {
                int tc = t0 + nt*8 + 2*tg;
                if (tc + 1 < TT) op[tc + 1] = acc3[mt][nt][r*2+0];
                if (tc + 2 < TT) op[tc + 2] = acc3[mt][nt][r*2+1];
            }
        }
    if (blockIdx.x == 0) out[((size_t)b*256 + tid)*TT] = 0.f;
}

// ===========================================================================
extern "C" void kernel_launch(void* const* d_in, const int* in_sizes, int n_in,
                              void* d_out, int out_size)
{
    const float* features   = (const float*)d_in[0];
    const int*   tokens     = (const int*)  d_in[1];
    const float* embed      = (const float*)d_in[2];
    const float* cond_W     = (const float*)d_in[3];
    const float* cond_b     = (const float*)d_in[4];
    const float* dilate_W   = (const float*)d_in[5];
    const float* dilate_b   = (const float*)d_in[6];
    const float* res_W      = (const float*)d_in[7];
    const float* res_b      = (const float*)d_in[8];
    const float* skip_W     = (const float*)d_in[9];
    const float* skip_b     = (const float*)d_in[10];
    const float* conv_out_W = (const float*)d_in[11];
    const float* conv_end_W = (const float*)d_in[12];
    float* outp = (float*)d_out;

    float* out_r   = outp;
    float* inact_r = outp + INACT_OFF;
    float* cond_r  = outp + COND_OFF;

    float *x0, *x1;
    __half *ah, *al;
    uint4 *wdh, *wdl, *wsh, *wsl, *wrh, *wrl, *wch, *wcl, *woh, *weh;
    cudaGetSymbolAddress((void**)&x0,  g_x0);
    cudaGetSymbolAddress((void**)&x1,  g_x1);
    cudaGetSymbolAddress((void**)&ah,  g_act_h);
    cudaGetSymbolAddress((void**)&al,  g_act_l);
    cudaGetSymbolAddress((void**)&wdh, g_wd_h);
    cudaGetSymbolAddress((void**)&wdl, g_wd_l);
    cudaGetSymbolAddress((void**)&wsh, g_ws_h);
    cudaGetSymbolAddress((void**)&wsl, g_ws_l);
    cudaGetSymbolAddress((void**)&wrh, g_wr_h);
    cudaGetSymbolAddress((void**)&wrl, g_wr_l);
    cudaGetSymbolAddress((void**)&wch, g_wc_h);
    cudaGetSymbolAddress((void**)&wcl, g_wc_l);
    cudaGetSymbolAddress((void**)&woh, g_wo_h);
    cudaGetSymbolAddress((void**)&weh, g_we_h);

    static const int DIL[LLC] = {1,2,4,8,16,32,64,128,256,1,2,4,8,16,32,64};

    cudaFuncSetAttribute(cond_mma2_kernel,  cudaFuncAttributeMaxDynamicSharedMemorySize, C2_SMEM);
    cudaFuncSetAttribute(layer_mma4_kernel, cudaFuncAttributeMaxDynamicSharedMemorySize, L4_SMEM);
    cudaFuncSetAttribute(skiphead2_kernel,  cudaFuncAttributeMaxDynamicSharedMemorySize, T2_SMEM);

    pack_dilate<<<128, 256>>>(dilate_W, wdh, wdl);
    pack_cond<<<128, 256>>>(cond_W, wch, wcl);
    pack_skip<<<128, 256>>>(skip_W, wsh, wsl);
    pack_res<<<30, 256>>>(res_W, wrh, wrl);
    pack_w256<<<32, 256>>>(conv_out_W, woh);
    pack_w256<<<32, 256>>>(conv_end_W, weh);

    embed_kernel<<<dim3(TT/256, BB), 256>>>(tokens, embed, x0);
    cond_mma2_kernel<<<dim3(TT/64, LLC, BB), 256, C2_SMEM>>>(features, wch, wcl, cond_b, cond_r);

    float* xi = x0;
    float* xo = x1;
    for (int i = 0; i < LLC; i++) {
        layer_mma4_kernel<<<dim3(TT/64, BB), 256, L4_SMEM>>>(
            xi, xo, wdh, wdl, dilate_b, wrh, wrl, res_b,
            cond_r, inact_r, ah, al,
            i, DIL[i], (i == LLC-1) ? 1 : 0);
        float* t = xi; xi = xo; xo = t;
    }

    skiphead2_kernel<<<dim3(TT/64, BB), 256, T2_SMEM>>>(
        ah, al, wsh, wsl, skip_b, woh, weh, out_r);
}

// round 10
// speedup vs baseline: 1.6099x; 1.0901x over previous
#include <cuda_runtime.h>
#include <cuda_fp16.h>
#include <math.h>
#include <stdint.h>

// Problem constants
#define BB 4
#define TT 8192
#define CC 128
#define RRC 64       // residual channels
#define SSC 256      // skip channels
#define LLC 16

// Output region offsets (pytree flatten order: out, in_acts, cond)
#define OUT_SZ     (BB*256*TT)
#define INACT_OFF  (OUT_SZ)
#define INACT_SZ   (BB*LLC*128*TT)
#define COND_OFF   (INACT_OFF + INACT_SZ)

#define SQRT_HALF 0.70710678118654752440f

// Scratch (device globals; no allocation allowed)
__device__ float g_x0[BB*RRC*TT];
__device__ float g_x1[BB*RRC*TT];

// Gated activations, fp16 hi/lo planes, layout [l][b][t][64ch]
__device__ __align__(16) __half g_act_h[LLC*BB*TT*64];
__device__ __align__(16) __half g_act_l[LLC*BB*TT*64];

// Pre-packed A-operand fragments (fp16 hi/lo), mma.m16n8k16 layout.
__device__ uint4 g_wd_h[LLC*2048];
__device__ uint4 g_wd_l[LLC*2048];
__device__ uint4 g_ws_h[LLC*2048];
__device__ uint4 g_ws_l[LLC*2048];
__device__ uint4 g_wr_h[15*512];
__device__ uint4 g_wr_l[15*512];
__device__ uint4 g_wc_h[LLC*2048];  // cond_W frags (hi/lo)
__device__ uint4 g_wc_l[LLC*2048];
__device__ uint4 g_wo_h[8192];      // conv_out_W frags (hi only)
__device__ uint4 g_we_h[8192];      // conv_end_W frags (hi only)

// ===========================================================================
// helpers
// ===========================================================================
__device__ __forceinline__ uint32_t smem_u32(const void* p) {
    uint32_t a;
    asm("{ .reg .u64 t; cvta.to.shared.u64 t, %1; cvt.u32.u64 %0, t; }" : "=r"(a) : "l"(p));
    return a;
}
__device__ __forceinline__ void ldsm4(uint32_t* r, uint32_t a) {
    asm volatile("ldmatrix.sync.aligned.m8n8.x4.shared.b16 {%0,%1,%2,%3}, [%4];"
        : "=r"(r[0]), "=r"(r[1]), "=r"(r[2]), "=r"(r[3]) : "r"(a));
}
__device__ __forceinline__ void mma16816(float* d, const uint32_t* a, const uint32_t* b) {
    asm volatile(
        "mma.sync.aligned.m16n8k16.row.col.f32.f16.f16.f32 "
        "{%0,%1,%2,%3}, {%4,%5,%6,%7}, {%8,%9}, {%0,%1,%2,%3};"
        : "+f"(d[0]), "+f"(d[1]), "+f"(d[2]), "+f"(d[3])
        : "r"(a[0]), "r"(a[1]), "r"(a[2]), "r"(a[3]), "r"(b[0]), "r"(b[1]));
}
__device__ __forceinline__ void ldB(uint32_t* fr, const char* sb, int off, int stride,
                                    int n0, int k0, int lane) {
    uint32_t a = smem_u32(sb + off) +
        (uint32_t)(((n0 + ((lane >> 4) & 1) * 8 + (lane & 7)) * stride
                    + k0 + ((lane >> 3) & 1) * 8) << 1);
    ldsm4(fr, a);
}
__device__ __forceinline__ void split2(float v, __half& h, __half& l) {
    h = __float2half_rn(v);
    l = __float2half_rn(v - __half2float(h));
}
__device__ __forceinline__ uint32_t packh2(__half a, __half b) {
    __half2 h = __halves2half2(a, b);
    return *(uint32_t*)&h;
}

#define CP_ASYNC16(dst, src) \
    asm volatile("cp.async.ca.shared.global [%0], [%1], 16;" :: "r"(dst), "l"(src))
#define CP_COMMIT() asm volatile("cp.async.commit_group;" ::: "memory")
#define CP_WAIT0()  asm volatile("cp.async.wait_group 0;" ::: "memory")

// ===========================================================================
// merged weight pre-pack kernel (one launch for all weight buffers)
// ===========================================================================
__device__ __forceinline__ void pack8(const float* v, uint4& hi, uint4& lo) {
    __half eh[8], el[8];
    #pragma unroll
    for (int i = 0; i < 8; i++) split2(v[i], eh[i], el[i]);
    hi.x = packh2(eh[0], eh[1]); hi.y = packh2(eh[2], eh[3]);
    hi.z = packh2(eh[4], eh[5]); hi.w = packh2(eh[6], eh[7]);
    lo.x = packh2(el[0], el[1]); lo.y = packh2(el[2], el[3]);
    lo.z = packh2(el[4], el[5]); lo.w = packh2(el[6], el[7]);
}

// grid 478 x 256: [0,128) dilate, [128,256) cond, [256,384) skip,
// [384,414) res, [414,446) Wout, [446,478) Wend
__global__ void pack_all_kernel(const float* __restrict__ dilate_W,
                                const float* __restrict__ cond_W,
                                const float* __restrict__ skip_W,
                                const float* __restrict__ res_W,
                                const float* __restrict__ Wout,
                                const float* __restrict__ Wend,
                                uint4* __restrict__ wdh, uint4* __restrict__ wdl,
                                uint4* __restrict__ wch, uint4* __restrict__ wcl,
                                uint4* __restrict__ wsh, uint4* __restrict__ wsl,
                                uint4* __restrict__ wrh, uint4* __restrict__ wrl,
                                uint4* __restrict__ woh, uint4* __restrict__ weh)
{
    const int bx = blockIdx.x, tid = threadIdx.x;
    static const int dr[8] = {0,0,8,8,0,0,8,8};
    static const int dc[8] = {0,1,0,1,8,9,8,9};

    if (bx < 128) {                       // dilate
        int idx = bx*256 + tid;
        int lane = idx & 31, fi = idx >> 5;
        int ks = fi & 7, mt = (fi >> 3) & 7, l = fi >> 6;
        int r = mt*16 + (lane >> 2), cb = ks*16 + (lane & 3)*2;
        float v[8];
        #pragma unroll
        for (int i = 0; i < 8; i++) {
            int row = r + dr[i], col = cb + dc[i];
            v[i] = (col < 64)
                ? dilate_W[((l*128 + row)*64 + col)*2 + 0]
                : dilate_W[((l*128 + row)*64 + (col - 64))*2 + 1];
        }
        uint4 hi, lo; pack8(v, hi, lo);
        wdh[idx] = hi; wdl[idx] = lo;
    } else if (bx < 256) {                // cond
        int idx = (bx-128)*256 + tid;
        int lane = idx & 31, fi = idx >> 5;
        int ks = fi & 7, mt = (fi >> 3) & 7, l = fi >> 6;
        int r = mt*16 + (lane >> 2), cb = ks*16 + (lane & 3)*2;
        float v[8];
        #pragma unroll
        for (int i = 0; i < 8; i++)
            v[i] = cond_W[((size_t)(l*128 + r + dr[i]))*CC + cb + dc[i]];
        uint4 hi, lo; pack8(v, hi, lo);
        wch[idx] = hi; wcl[idx] = lo;
    } else if (bx < 384) {                // skip
        int idx = (bx-256)*256 + tid;
        int lane = idx & 31, fi = idx >> 5;
        int ks = fi & 3, mt = (fi >> 2) & 15, l = fi >> 6;
        int r = mt*16 + (lane >> 2), cb = ks*16 + (lane & 3)*2;
        float v[8];
        #pragma unroll
        for (int i = 0; i < 8; i++)
            v[i] = skip_W[((size_t)l*256 + r + dr[i])*64 + cb + dc[i]];
        uint4 hi, lo; pack8(v, hi, lo);
        wsh[idx] = hi; wsl[idx] = lo;
    } else if (bx < 414) {                // res
        int idx = (bx-384)*256 + tid;
        if (idx >= 7680) return;
        int lane = idx & 31, fi = idx >> 5;
        int ks = fi & 3, mt = (fi >> 2) & 3, l = fi >> 4;
        int r = mt*16 + (lane >> 2), cb = ks*16 + (lane & 3)*2;
        float v[8];
        #pragma unroll
        for (int i = 0; i < 8; i++)
            v[i] = res_W[((size_t)l*64 + r + dr[i])*64 + cb + dc[i]];
        uint4 hi, lo; pack8(v, hi, lo);
        wrh[idx] = hi; wrl[idx] = lo;
    } else {                              // Wout / Wend (hi only)
        const float* W = (bx < 446) ? Wout : Wend;
        uint4* outp    = (bx < 446) ? woh : weh;
        int idx = ((bx < 446) ? (bx-414) : (bx-446))*256 + tid;
        int lane = idx & 31, fi = idx >> 5;
        int ks = fi & 15, mt = fi >> 4;
        int r = mt*16 + (lane >> 2), cb = ks*16 + (lane & 3)*2;
        __half eh[8];
        #pragma unroll
        for (int i = 0; i < 8; i++)
            eh[i] = __float2half_rn(W[(r + dr[i])*256 + cb + dc[i]]);
        uint4 hi;
        hi.x = packh2(eh[0], eh[1]); hi.y = packh2(eh[2], eh[3]);
        hi.z = packh2(eh[4], eh[5]); hi.w = packh2(eh[6], eh[7]);
        outp[idx] = hi;
    }
}

// ===========================================================================
// embed
// ===========================================================================
__global__ void embed_kernel(const int* __restrict__ tokens,
                             const float* __restrict__ embed,
                             float* __restrict__ x0)
{
    __shared__ int tok[256];
    const int t0 = blockIdx.x * 256;
    const int b  = blockIdx.y;
    tok[threadIdx.x] = tokens[b*TT + t0 + threadIdx.x];
    __syncthreads();
    const int v = tok[threadIdx.x];
    #pragma unroll 4
    for (int r = 0; r < RRC; r++)
        x0[(b*RRC + r)*TT + t0 + threadIdx.x] = embed[v*RRC + r];
}

// ===========================================================================
// cond v2 (unchanged from R9)
// ===========================================================================
#define C2_FH 0
#define C2_FL 17408
#define C2_SMEM 34816

__global__ void __launch_bounds__(256, 3)
cond_mma2_kernel(const float* __restrict__ features,
                 const uint4* __restrict__ wc_h, const uint4* __restrict__ wc_l,
                 const float* __restrict__ cond_b,
                 float* __restrict__ cond_out)
{
    extern __shared__ char sb[];
    const int tid = threadIdx.x, wid = tid >> 5, lane = tid & 31;
    const int g = lane >> 2, tg = lane & 3;
    const int t0 = blockIdx.x * 64;
    const int l  = blockIdx.y;
    const int b  = blockIdx.z;

    {
        __half* FH = (__half*)(sb + C2_FH);
        __half* FL = (__half*)(sb + C2_FL);
        for (int e = tid; e < 8192; e += 256) {
            int t = e & 63, k = e >> 6;
            float v = features[((size_t)b*CC + k)*TT + t0 + t];
            __half h, lo; split2(v, h, lo);
            FH[t*136 + k] = h; FL[t*136 + k] = lo;
        }
    }
    __syncthreads();

    const int mi = wid >> 1, ni = wid & 1;
    const int m0 = mi * 32, n0 = ni * 32;

    float acc[2][4][4] = {};
    {
        const uint4* ph = wc_h + (size_t)l * 2048;
        const uint4* pl = wc_l + (size_t)l * 2048;
        for (int ks = 0; ks < 8; ks++) {
            uint4 A0h = ph[((mi*2    )*8 + ks)*32 + lane];
            uint4 A1h = ph[((mi*2 + 1)*8 + ks)*32 + lane];
            uint4 A0l = pl[((mi*2    )*8 + ks)*32 + lane];
            uint4 A1l = pl[((mi*2 + 1)*8 + ks)*32 + lane];
            #pragma unroll
            for (int p = 0; p < 2; p++) {
                uint32_t bh[4], bl[4];
                ldB(bh, sb, C2_FH, 136, n0 + p*16, ks*16, lane);
                ldB(bl, sb, C2_FL, 136, n0 + p*16, ks*16, lane);
                #pragma unroll
                for (int q = 0; q < 2; q++) {
                    int nt = p*2 + q;
                    mma16816(acc[0][nt], (const uint32_t*)&A0h, &bh[q*2]);
                    mma16816(acc[0][nt], (const uint32_t*)&A0h, &bl[q*2]);
                    mma16816(acc[0][nt], (const uint32_t*)&A0l, &bh[q*2]);
                    mma16816(acc[1][nt], (const uint32_t*)&A1h, &bh[q*2]);
                    mma16816(acc[1][nt], (const uint32_t*)&A1h, &bl[q*2]);
                    mma16816(acc[1][nt], (const uint32_t*)&A1l, &bh[q*2]);
                }
            }
        }
    }

    #pragma unroll
    for (int mt = 0; mt < 2; mt++)
        #pragma unroll
        for (int r = 0; r < 2; r++) {
            int o = m0 + mt*16 + r*8 + g;
            float bias = cond_b[l*128 + o];
            float* row = cond_out + ((size_t)(b*LLC + l)*128 + o)*TT + t0;
            #pragma unroll
            for (int nt = 0; nt < 4; nt++) {
                int tc = n0 + nt*8 + 2*tg;
                float2 rv = make_float2(acc[mt][nt][r*2+0] + bias,
                                        acc[mt][nt][r*2+1] + bias);
                *(float2*)(row + tc) = rv;
            }
        }
}

// ===========================================================================
// layer v5: t-tile 32, 128 threads, 6 CTAs/SM target. grid (T/32=256, B).
// cond read directly from gmem in epilogue (no CND smem / cp.async).
// smem: phase1 XH[32][136] @0 (8704), XL @8704 -> 17408
//       phase2 ABUF fp32[128][34] @0 (17408), AH[32][72] @17408, AL @22016
// total 26624
// ===========================================================================
#define L5_XH   0
#define L5_XL   8704
#define L5_ABUF 0
#define L5_AH   17408
#define L5_AL   22016
#define L5_SMEM 26624

__global__ void __launch_bounds__(128, 6)
layer_mma5_kernel(const float* __restrict__ x_in,
                  float* __restrict__ x_out,
                  const uint4* __restrict__ wd_h, const uint4* __restrict__ wd_l,
                  const float* __restrict__ dilate_b,
                  const uint4* __restrict__ wr_h, const uint4* __restrict__ wr_l,
                  const float* __restrict__ res_b,
                  const float* __restrict__ cond_g,
                  float* __restrict__ inacts_g,
                  __half* __restrict__ act_h, __half* __restrict__ act_l,
                  int layer, int dil, int last)
{
    extern __shared__ char sb[];
    const int tid = threadIdx.x, wid = tid >> 5, lane = tid & 31;
    const int g = lane >> 2, tg = lane & 3;
    const int t0 = blockIdx.x * 32;
    const int b  = blockIdx.y;

    // ---- stage X halves: [t:32][ks:128]
    {
        __half* XH = (__half*)(sb + L5_XH);
        __half* XL = (__half*)(sb + L5_XL);
        const float* xb = x_in + (size_t)b * RRC * TT;
        for (int e = tid; e < 4096; e += 128) {
            int t = e & 31, ks = e >> 5;
            float v;
            if (ks < 64) {
                int tp = t0 + t - dil;
                v = (tp >= 0) ? xb[ks*TT + tp] : 0.f;
            } else {
                v = xb[(ks - 64)*TT + t0 + t];
            }
            __half h, lo; split2(v, h, lo);
            XH[t*136 + ks] = h; XL[t*136 + ks] = lo;
        }
    }
    __syncthreads();

    // ---- GEMM1: ia[128 o][32 t] = Wd @ Xcat (K=128), 3-pass
    // warp wid owns m0 = wid*32, full N=32
    const int m0 = wid * 32;
    float acc[2][4][4] = {};
    {
        const uint4* ph = wd_h + (size_t)layer * 2048;
        const uint4* pl = wd_l + (size_t)layer * 2048;
        for (int ks = 0; ks < 8; ks++) {
            uint4 A0h = ph[((wid*2    )*8 + ks)*32 + lane];
            uint4 A1h = ph[((wid*2 + 1)*8 + ks)*32 + lane];
            uint4 A0l = pl[((wid*2    )*8 + ks)*32 + lane];
            uint4 A1l = pl[((wid*2 + 1)*8 + ks)*32 + lane];
            #pragma unroll
            for (int p = 0; p < 2; p++) {
                uint32_t bh[4], bl[4];
                ldB(bh, sb, L5_XH, 136, p*16, ks*16, lane);
                ldB(bl, sb, L5_XL, 136, p*16, ks*16, lane);
                #pragma unroll
                for (int q = 0; q < 2; q++) {
                    int nt = p*2 + q;
                    mma16816(acc[0][nt], (const uint32_t*)&A0h, &bh[q*2]);
                    mma16816(acc[0][nt], (const uint32_t*)&A0h, &bl[q*2]);
                    mma16816(acc[0][nt], (const uint32_t*)&A0l, &bh[q*2]);
                    mma16816(acc[1][nt], (const uint32_t*)&A1h, &bh[q*2]);
                    mma16816(acc[1][nt], (const uint32_t*)&A1h, &bl[q*2]);
                    mma16816(acc[1][nt], (const uint32_t*)&A1l, &bh[q*2]);
                }
            }
        }
    }
    __syncthreads();   // X reads done before ABUF aliases X

    // ---- epilogue1: ia -> gmem in_acts; a = ia + cond(gmem) -> ABUF
    {
        float* abuf = (float*)(sb + L5_ABUF);
        #pragma unroll
        for (int mt = 0; mt < 2; mt++)
            #pragma unroll
            for (int r = 0; r < 2; r++) {
                int o = m0 + mt*16 + r*8 + g;
                float bias = dilate_b[layer*128 + o];
                size_t rowoff = ((size_t)(b*LLC + layer)*128 + o)*TT + t0;
                float*       iap = inacts_g + rowoff;
                const float* cp  = cond_g + rowoff;
                float* ab = abuf + o*34;
                #pragma unroll
                for (int nt = 0; nt < 4; nt++) {
                    int tc = nt*8 + 2*tg;
                    float2 cv = *(const float2*)(cp + tc);
                    float ia0 = acc[mt][nt][r*2+0] + bias;
                    float ia1 = acc[mt][nt][r*2+1] + bias;
                    *(float2*)(iap + tc) = make_float2(ia0, ia1);
                    *(float2*)(ab + tc) = make_float2(ia0 + cv.x, ia1 + cv.y);
                }
            }
    }
    __syncthreads();

    // ---- gated activation -> AH/AL
    {
        float* abuf = (float*)(sb + L5_ABUF);
        __half* AH = (__half*)(sb + L5_AH);
        __half* AL = (__half*)(sb + L5_AL);
        for (int e = tid; e < 2048; e += 128) {
            int t = e & 31, kk = e >> 5;
            float a0 = abuf[kk*34 + t];
            float a1 = abuf[(kk + 64)*34 + t];
            float act = tanhf(a0) * (1.f / (1.f + __expf(-a1)));
            __half h, lo; split2(act, h, lo);
            AH[t*72 + kk] = h; AL[t*72 + kk] = lo;
        }
    }
    __syncthreads();

    // ---- store act planes (consumed by skiphead)
    {
        uint4* gh = (uint4*)(act_h + ((size_t)(layer*BB + b)*TT + t0)*64);
        uint4* gl = (uint4*)(act_l + ((size_t)(layer*BB + b)*TT + t0)*64);
        for (int i = tid; i < 256; i += 128) {
            int t = i >> 3, j = i & 7;
            gh[t*8 + j] = *(const uint4*)(sb + L5_AH + t*144 + j*16);
            gl[t*8 + j] = *(const uint4*)(sb + L5_AL + t*144 + j*16);
        }
    }

    // ---- GEMM3: res (M=64, N=32, K=64), 3-pass; residual x update
    if (!last) {
        const int mi3 = wid >> 1, ni3 = wid & 1;
        const int m0r = mi3 * 32, n0r = ni3 * 16;
        const uint4* ph = wr_h + (size_t)layer * 512;
        const uint4* pl = wr_l + (size_t)layer * 512;
        float acc3[2][2][4] = {};
        for (int ks = 0; ks < 4; ks++) {
            uint4 A0h = ph[((mi3*2    )*4 + ks)*32 + lane];
            uint4 A1h = ph[((mi3*2 + 1)*4 + ks)*32 + lane];
            uint4 A0l = pl[((mi3*2    )*4 + ks)*32 + lane];
            uint4 A1l = pl[((mi3*2 + 1)*4 + ks)*32 + lane];
            uint32_t bh[4], bl[4];
            ldB(bh, sb, L5_AH, 72, n0r, ks*16, lane);
            ldB(bl, sb, L5_AL, 72, n0r, ks*16, lane);
            #pragma unroll
            for (int q = 0; q < 2; q++) {
                mma16816(acc3[0][q], (const uint32_t*)&A0h, &bh[q*2]);
                mma16816(acc3[0][q], (const uint32_t*)&A0h, &bl[q*2]);
                mma16816(acc3[0][q], (const uint32_t*)&A0l, &bh[q*2]);
                mma16816(acc3[1][q], (const uint32_t*)&A1h, &bh[q*2]);
                mma16816(acc3[1][q], (const uint32_t*)&A1h, &bl[q*2]);
                mma16816(acc3[1][q], (const uint32_t*)&A1l, &bh[q*2]);
            }
        }
        #pragma unroll
        for (int mt = 0; mt < 2; mt++)
            #pragma unroll
            for (int r = 0; r < 2; r++) {
                int o = m0r + mt*16 + r*8 + g;
                float rb = res_b[layer*RRC + o];
                const float* xi = x_in  + ((size_t)b*RRC + o)*TT + t0;
                float*       xo = x_out + ((size_t)b*RRC + o)*TT + t0;
                #pragma unroll
                for (int nt = 0; nt < 2; nt++) {
                    int tc = n0r + nt*8 + 2*tg;
                    float2 xv = *(const float2*)(xi + tc);
                    float2 rv;
                    rv.x = (acc3[mt][nt][r*2+0] + rb + xv.x) * SQRT_HALF;
                    rv.y = (acc3[mt][nt][r*2+1] + rb + xv.y) * SQRT_HALF;
                    *(float2*)(xo + tc) = rv;
                }
            }
    }
}

// ===========================================================================
// skiphead v2 (unchanged from R8/R9)
// ===========================================================================
#define TB_SZ  18432
#define T2_SMEM 36864

__global__ void __launch_bounds__(256, 2)
skiphead2_kernel(const __half* __restrict__ act_h, const __half* __restrict__ act_l,
                 const uint4* __restrict__ ws_h, const uint4* __restrict__ ws_l,
                 const float* __restrict__ skip_b,
                 const uint4* __restrict__ wo_h, const uint4* __restrict__ we_h,
                 float* __restrict__ out)
{
    extern __shared__ char sb[];
    uint32_t sb_u = smem_u32(sb);
    const int tid = threadIdx.x, wid = tid >> 5, lane = tid & 31;
    const int g = lane >> 2, tg = lane & 3;
    const int t0 = blockIdx.x * 64;
    const int b  = blockIdx.y;

    float acc[2][8][4] = {};   // skip acc: o = wid*32 + mt*16 + r*8 + g

    auto stage = [&](int l, int buf) {
        const uint4* gh = (const uint4*)(act_h + ((size_t)(l*BB + b)*TT + t0)*64);
        const uint4* gl = (const uint4*)(act_l + ((size_t)(l*BB + b)*TT + t0)*64);
        uint32_t dh = sb_u + buf*TB_SZ;
        uint32_t dl = dh + 9216;
        for (int i = tid; i < 512; i += 256) {
            int t = i >> 3, j = i & 7;
            CP_ASYNC16(dh + t*144 + j*16, gh + t*8 + j);
            CP_ASYNC16(dl + t*144 + j*16, gl + t*8 + j);
        }
        CP_COMMIT();
    };

    stage(0, 0);
    CP_WAIT0();
    __syncthreads();

    for (int l = 0; l < LLC; l++) {
        int cur = l & 1;
        if (l + 1 < LLC) stage(l + 1, cur ^ 1);

        int offH = cur*TB_SZ, offL = offH + 9216;
        const uint4* ph = ws_h + (size_t)l * 2048;
        const uint4* pl = ws_l + (size_t)l * 2048;
        for (int ks = 0; ks < 4; ks++) {
            uint4 A0h = ph[((wid*2    )*4 + ks)*32 + lane];
            uint4 A1h = ph[((wid*2 + 1)*4 + ks)*32 + lane];
            uint4 A0l = pl[((wid*2    )*4 + ks)*32 + lane];
            uint4 A1l = pl[((wid*2 + 1)*4 + ks)*32 + lane];
            #pragma unroll
            for (int p = 0; p < 4; p++) {
                uint32_t bh[4], bl[4];
                ldB(bh, sb, offH, 72, p*16, ks*16, lane);
                ldB(bl, sb, offL, 72, p*16, ks*16, lane);
                #pragma unroll
                for (int q = 0; q < 2; q++) {
                    int nt = p*2 + q;
                    mma16816(acc[0][nt], (const uint32_t*)&A0h, &bh[q*2]);
                    mma16816(acc[0][nt], (const uint32_t*)&A0h, &bl[q*2]);
                    mma16816(acc[0][nt], (const uint32_t*)&A0l, &bh[q*2]);
                    mma16816(acc[1][nt], (const uint32_t*)&A1h, &bh[q*2]);
                    mma16816(acc[1][nt], (const uint32_t*)&A1h, &bl[q*2]);
                    mma16816(acc[1][nt], (const uint32_t*)&A1l, &bh[q*2]);
                }
            }
        }
        if (l + 1 < LLC) CP_WAIT0();
        __syncthreads();
    }

    // skip bias sum + relu -> H fp16 [t][o:256] (aliases buffers)
    {
        __half* H = (__half*)sb;
        #pragma unroll
        for (int mt = 0; mt < 2; mt++)
            #pragma unroll
            for (int r = 0; r < 2; r++) {
                int o = wid*32 + mt*16 + r*8 + g;
                float bs = 0.f;
                #pragma unroll
                for (int l = 0; l < LLC; l++) bs += skip_b[l*SSC + o];
                #pragma unroll
                for (int nt = 0; nt < 8; nt++) {
                    int t = nt*8 + tg*2;
                    H[t*264 + o]     = __float2half_rn(fmaxf(acc[mt][nt][r*2+0] + bs, 0.f));
                    H[(t+1)*264 + o] = __float2half_rn(fmaxf(acc[mt][nt][r*2+1] + bs, 0.f));
                }
            }
    }
    __syncthreads();

    // head GEMM A: h2 = relu(Wout @ h) (single-pass)
    float acc2[2][8][4] = {};
    for (int ks = 0; ks < 16; ks++) {
        uint4 A0 = wo_h[((wid*2    )*16 + ks)*32 + lane];
        uint4 A1 = wo_h[((wid*2 + 1)*16 + ks)*32 + lane];
        #pragma unroll
        for (int p = 0; p < 4; p++) {
            uint32_t bh[4];
            ldB(bh, sb, 0, 264, p*16, ks*16, lane);
            #pragma unroll
            for (int q = 0; q < 2; q++) {
                int nt = p*2 + q;
                mma16816(acc2[0][nt], (const uint32_t*)&A0, &bh[q*2]);
                mma16816(acc2[1][nt], (const uint32_t*)&A1, &bh[q*2]);
            }
        }
    }
    __syncthreads();
    {
        __half* H = (__half*)sb;
        #pragma unroll
        for (int mt = 0; mt < 2; mt++)
            #pragma unroll
            for (int r = 0; r < 2; r++) {
                int o = wid*32 + mt*16 + r*8 + g;
                #pragma unroll
                for (int nt = 0; nt < 8; nt++) {
                    int t = nt*8 + tg*2;
                    H[t*264 + o]     = __float2half_rn(fmaxf(acc2[mt][nt][r*2+0], 0.f));
                    H[(t+1)*264 + o] = __float2half_rn(fmaxf(acc2[mt][nt][r*2+1], 0.f));
                }
            }
    }
    __syncthreads();

    // head GEMM B: out = Wend @ h2, shifted right by 1
    float acc3[2][8][4] = {};
    for (int ks = 0; ks < 16; ks++) {
        uint4 A0 = we_h[((wid*2    )*16 + ks)*32 + lane];
        uint4 A1 = we_h[((wid*2 + 1)*16 + ks)*32 + lane];
        #pragma unroll
        for (int p = 0; p < 4; p++) {
            uint32_t bh[4];
            ldB(bh, sb, 0, 264, p*16, ks*16, lane);
            #pragma unroll
            for (int q = 0; q < 2; q++) {
                int nt = p*2 + q;
                mma16816(acc3[0][nt], (const uint32_t*)&A0, &bh[q*2]);
                mma16816(acc3[1][nt], (const uint32_t*)&A1, &bh[q*2]);
            }
        }
    }
    #pragma unroll
    for (int mt = 0; mt < 2; mt++)
        #pragma unroll
        for (int r = 0; r < 2; r++) {
            int o = wid*32 + mt*16 + r*8 + g;
            float* op = out + ((size_t)b*256 + o)*TT;
            #pragma unroll
            for (int nt = 0; nt < 8; nt++) {
                int tc = t0 + nt*8 + 2*tg;
                if (tc + 1 < TT) op[tc + 1] = acc3[mt][nt][r*2+0];
                if (tc + 2 < TT) op[tc + 2] = acc3[mt][nt][r*2+1];
            }
        }
    if (blockIdx.x == 0) out[((size_t)b*256 + tid)*TT] = 0.f;
}

// ===========================================================================
extern "C" void kernel_launch(void* const* d_in, const int* in_sizes, int n_in,
                              void* d_out, int out_size)
{
    const float* features   = (const float*)d_in[0];
    const int*   tokens     = (const int*)  d_in[1];
    const float* embed      = (const float*)d_in[2];
    const float* cond_W     = (const float*)d_in[3];
    const float* cond_b     = (const float*)d_in[4];
    const float* dilate_W   = (const float*)d_in[5];
    const float* dilate_b   = (const float*)d_in[6];
    const float* res_W      = (const float*)d_in[7];
    const float* res_b      = (const float*)d_in[8];
    const float* skip_W     = (const float*)d_in[9];
    const float* skip_b     = (const float*)d_in[10];
    const float* conv_out_W = (const float*)d_in[11];
    const float* conv_end_W = (const float*)d_in[12];
    float* outp = (float*)d_out;

    float* out_r   = outp;
    float* inact_r = outp + INACT_OFF;
    float* cond_r  = outp + COND_OFF;

    float *x0, *x1;
    __half *ah, *al;
    uint4 *wdh, *wdl, *wsh, *wsl, *wrh, *wrl, *wch, *wcl, *woh, *weh;
    cudaGetSymbolAddress((void**)&x0,  g_x0);
    cudaGetSymbolAddress((void**)&x1,  g_x1);
    cudaGetSymbolAddress((void**)&ah,  g_act_h);
    cudaGetSymbolAddress((void**)&al,  g_act_l);
    cudaGetSymbolAddress((void**)&wdh, g_wd_h);
    cudaGetSymbolAddress((void**)&wdl, g_wd_l);
    cudaGetSymbolAddress((void**)&wsh, g_ws_h);
    cudaGetSymbolAddress((void**)&wsl, g_ws_l);
    cudaGetSymbolAddress((void**)&wrh, g_wr_h);
    cudaGetSymbolAddress((void**)&wrl, g_wr_l);
    cudaGetSymbolAddress((void**)&wch, g_wc_h);
    cudaGetSymbolAddress((void**)&wcl, g_wc_l);
    cudaGetSymbolAddress((void**)&woh, g_wo_h);
    cudaGetSymbolAddress((void**)&weh, g_we_h);

    static const int DIL[LLC] = {1,2,4,8,16,32,64,128,256,1,2,4,8,16,32,64};

    cudaFuncSetAttribute(cond_mma2_kernel,  cudaFuncAttributeMaxDynamicSharedMemorySize, C2_SMEM);
    cudaFuncSetAttribute(layer_mma5_kernel, cudaFuncAttributeMaxDynamicSharedMemorySize, L5_SMEM);
    cudaFuncSetAttribute(skiphead2_kernel,  cudaFuncAttributeMaxDynamicSharedMemorySize, T2_SMEM);

    pack_all_kernel<<<478, 256>>>(dilate_W, cond_W, skip_W, res_W, conv_out_W, conv_end_W,
                                  wdh, wdl, wch, wcl, wsh, wsl, wrh, wrl, woh, weh);

    embed_kernel<<<dim3(TT/256, BB), 256>>>(tokens, embed, x0);
    cond_mma2_kernel<<<dim3(TT/64, LLC, BB), 256, C2_SMEM>>>(features, wch, wcl, cond_b, cond_r);

    float* xi = x0;
    float* xo = x1;
    for (int i = 0; i < LLC; i++) {
        layer_mma5_kernel<<<dim3(TT/32, BB), 128, L5_SMEM>>>(
            xi, xo, wdh, wdl, dilate_b, wrh, wrl, res_b,
            cond_r, inact_r, ah, al,
            i, DIL[i], (i == LLC-1) ? 1 : 0);
        float* t = xi; xi = xo; xo = t;
    }

    skiphead2_kernel<<<dim3(TT/64, BB), 256, T2_SMEM>>>(
        ah, al, wsh, wsl, skip_b, woh, weh, out_r);
}